// round 10
// baseline (speedup 1.0000x reference)
#include <cuda_runtime.h>
#include <cuda_fp16.h>
#include <math.h>
#include <stdint.h>

typedef unsigned long long ull;

// ---------------- problem constants ----------------
#define T_DIM 64
#define B_DIM 32
#define C_DIM 256
#define V_DIM 25
#define H_DIM 8
#define HD_DIM 32
#define PLANE  (B_DIM * C_DIM * V_DIM)    // 204800
#define TOT    (T_DIM * PLANE)            // 13107200
#define NF     (T_DIM * B_DIM * V_DIM)    // 51200  (GEMM N)

// ---------------- device scratch ----------------
// split-plane layout: row r has 256 u32 words; words 0..127 = hi f16x2 pairs
// (k=2w,2w+1), words 128..255 = lo. Element (r,k): hi half at ushort idx r*512+k,
// lo half at r*512+256+k.
__device__ __align__(16) uint32_t g_wsp[4][C_DIM * 256];   // weights split  (1 MB)
__device__ __align__(16) uint32_t g_qsp[(size_t)NF * 256]; // qkv_in split; later attn split
__device__ __align__(16) uint32_t g_xsp[(size_t)NF * 256]; // x split

// fp32 tensors, [c][n] layout (addr = c*NF + t*800 + b*25 + v)
__device__ __align__(16) float g_yq[TOT];    // q bn-conv out; later proj bn-conv out
__device__ __align__(16) float g_yk[TOT];
__device__ __align__(16) float g_yv[TOT];
__device__ __align__(16) float g_qs[TOT];    // q spikes
__device__ __align__(16) float g_kvl[TOT];   // k_s * v_s

__device__ float g_scale[4][C_DIM];
__device__ float g_shift[4][C_DIM];
__device__ float g_topo[H_DIM][V_DIM * V_DIM];
__device__ float g_decay[C_DIM];

// ---------------- helpers ----------------
#define LO_SCALE 1024.0f
#define LO_INV   (1.0f / 1024.0f)

__device__ __forceinline__ uint32_t pack_split(float x) {
    __half h = __float2half_rn(x);
    float r = (x - __half2float(h)) * LO_SCALE;
    __half l = __float2half_rn(r);
    __half2 p = __halves2half2(h, l);   // low = h, high = l
    return *reinterpret_cast<uint32_t*>(&p);
}

// m16n8k16 f16 mma: acc(4 f32) += A(4x f16x2) x B(2x f16x2)
__device__ __forceinline__ void mma16(float* c, const uint32_t* a, const uint32_t* b) {
    asm volatile(
        "mma.sync.aligned.m16n8k16.row.col.f32.f16.f16.f32 "
        "{%0,%1,%2,%3}, {%4,%5,%6,%7}, {%8,%9}, {%0,%1,%2,%3};"
        : "+f"(c[0]), "+f"(c[1]), "+f"(c[2]), "+f"(c[3])
        : "r"(a[0]), "r"(a[1]), "r"(a[2]), "r"(a[3]), "r"(b[0]), "r"(b[1]));
}

// ---------------- K0: prep ----------------
struct PrepArgs {
    const float* w[4];
    const float* gamma[4];
    const float* beta[4];
    const float* mean[4];
    const float* var[4];
    const float* projb;
    const float* base;
    const float* learned;
    const float* sdw;
};

__global__ void k_prep(PrepArgs p) {
    int blk = blockIdx.x, tid = threadIdx.x;
    if (blk < 4) {
        // split weights into fp16 hi/lo planes
        unsigned short* W = reinterpret_cast<unsigned short*>(g_wsp[blk]);
        const float* w = p.w[blk];
        for (int idx = tid; idx < C_DIM * C_DIM; idx += 256) {
            int m = idx >> 8, k = idx & 255;
            uint32_t u = pack_split(w[idx]);
            W[m * 512 + k] = (unsigned short)(u & 0xFFFF);
            W[m * 512 + 256 + k] = (unsigned short)(u >> 16);
        }
        float sc = p.gamma[blk][tid] * rsqrtf(p.var[blk][tid] + 1e-5f);
        float sh = p.beta[blk][tid] - p.mean[blk][tid] * sc;
        if (blk == 3) sh += p.projb[tid] * sc;
        g_scale[blk][tid] = sc;
        g_shift[blk][tid] = sh;
    } else if (blk == 4) {
        if (tid < H_DIM * V_DIM) {
            int h = tid / V_DIM, i = tid - h * V_DIM;
            float l[V_DIM];
            float mx = -1e30f;
            for (int j = 0; j < V_DIM; j++) {
                l[j] = p.base[i * V_DIM + j] + 0.5f * p.learned[(h * V_DIM + i) * V_DIM + j];
                mx = fmaxf(mx, l[j]);
            }
            float sum = 0.f;
            for (int j = 0; j < V_DIM; j++) { l[j] = expf(l[j] - mx); sum += l[j]; }
            float inv = 1.f / sum;
            for (int j = 0; j < V_DIM; j++) g_topo[h][i * V_DIM + j] = l[j] * inv;
        }
    } else {
        float w = p.sdw[tid];
        float sg = 1.f / (1.f + expf(-w));
        g_decay[tid] = fminf(0.99f, fmaxf(0.01f, sg));
    }
}

// ---------------- K1: transpose + split x and qkv_in ----------------
// block = one (t,b). Two passes through a 25.6KB smem transpose buffer.
__global__ void k_trans(const float* __restrict__ x, const float* __restrict__ alpha) {
    __shared__ uint32_t sx[C_DIM * V_DIM];   // packed (hi,lo) per element, [c][v]
    __shared__ float alp[C_DIM];
    int tid = threadIdx.x;
    alp[tid] = alpha[tid];
    __syncthreads();

    int t = blockIdx.x >> 5;
    int b = blockIdx.x & 31;
    const float* xin = x + (size_t)t * PLANE + b * (C_DIM * V_DIM);
    const float* xpr = xin - PLANE;
    int nbase = t * 800 + b * V_DIM;
    unsigned short* XH = reinterpret_cast<unsigned short*>(g_xsp);
    unsigned short* QH = reinterpret_cast<unsigned short*>(g_qsp);

    // pass 1: x
    for (int idx = tid; idx < C_DIM * V_DIM; idx += 256)
        sx[idx] = pack_split(xin[idx]);
    __syncthreads();
    for (int odx = tid; odx < C_DIM * V_DIM; odx += 256) {
        int v = odx >> 8, c = odx & 255;
        uint32_t u = sx[c * V_DIM + v];
        size_t n = nbase + v;
        XH[n * 512 + c] = (unsigned short)(u & 0xFFFF);
        XH[n * 512 + 256 + c] = (unsigned short)(u >> 16);
    }
    __syncthreads();

    // pass 2: qkv_in = a*|dx| + (1-a)*x
    for (int idx = tid; idx < C_DIM * V_DIM; idx += 256) {
        int c = idx / V_DIM;
        float xv = xin[idx];
        float g = (t == 0) ? 0.f : fabsf(xv - xpr[idx]);
        float a = alp[c];
        sx[idx] = pack_split(a * g + (1.f - a) * xv);
    }
    __syncthreads();
    for (int odx = tid; odx < C_DIM * V_DIM; odx += 256) {
        int v = odx >> 8, c = odx & 255;
        uint32_t u = sx[c * V_DIM + v];
        size_t n = nbase + v;
        QH[n * 512 + c] = (unsigned short)(u & 0xFFFF);
        QH[n * 512 + 256 + c] = (unsigned short)(u >> 16);
    }
}

// ---------------- K2/K5: fp16x3 mma.sync GEMM, direct gmem operands ----------------
// Block tile 128x64, 256 threads (8 warps), warp tile 64x16, no smem, no syncs.
#define BM 128
#define BN 64
#define GTHREADS 256

__global__ void __launch_bounds__(GTHREADS, 2) k_gemm_mma(int pass) {
    int mt;
    const uint32_t* Bsp;
    float* out;
    if (pass == 0) {
        mt = blockIdx.z;
        Bsp = (mt == 2) ? g_xsp : g_qsp;
        out = (mt == 0) ? g_yq : (mt == 1) ? g_yk : g_yv;
    } else {
        mt = 3;
        Bsp = g_qsp;
        out = g_yq;
    }
    const uint32_t* Asp = g_wsp[mt];
    int m0 = blockIdx.y * BM;
    int n0 = blockIdx.x * BN;
    int tid = threadIdx.x;
    int lane = tid & 31, wid = tid >> 5;
    int wm = wid >> 2;   // 0..1 -> 64 rows
    int wn = wid & 3;    // 0..3 -> 16 cols
    int g = lane >> 2, c = lane & 3;

    const uint32_t* ap[4];
#pragma unroll
    for (int i = 0; i < 4; i++)
        ap[i] = Asp + (size_t)(m0 + wm * 64 + i * 16 + g) * 256;
    const uint32_t* bp0 = Bsp + (size_t)(n0 + (wn * 2 + 0) * 8 + g) * 256;
    const uint32_t* bp1 = Bsp + (size_t)(n0 + (wn * 2 + 1) * 8 + g) * 256;

    float acc1[4][2][4], acc2[4][2][4];
#pragma unroll
    for (int i = 0; i < 4; i++)
#pragma unroll
        for (int j = 0; j < 2; j++)
#pragma unroll
            for (int r = 0; r < 4; r++) { acc1[i][j][r] = 0.f; acc2[i][j][r] = 0.f; }

    int ko = c;
    uint32_t bh[2][2], bl[2][2];
    bh[0][0] = bp0[ko]; bh[0][1] = bp0[ko + 4];
    bl[0][0] = bp0[ko + 128]; bl[0][1] = bp0[ko + 132];
    bh[1][0] = bp1[ko]; bh[1][1] = bp1[ko + 4];
    bl[1][0] = bp1[ko + 128]; bl[1][1] = bp1[ko + 132];

    for (int kc = 0; kc < 16; kc++) {
        uint32_t nbh[2][2], nbl[2][2];
        if (kc < 15) {
            int k2 = ko + 8;
            nbh[0][0] = bp0[k2]; nbh[0][1] = bp0[k2 + 4];
            nbl[0][0] = bp0[k2 + 128]; nbl[0][1] = bp0[k2 + 132];
            nbh[1][0] = bp1[k2]; nbh[1][1] = bp1[k2 + 4];
            nbl[1][0] = bp1[k2 + 128]; nbl[1][1] = bp1[k2 + 132];
        }
#pragma unroll
        for (int i = 0; i < 4; i++) {
            uint32_t Ah[4], Al[4];
            const uint32_t* a = ap[i];
            Ah[0] = a[ko];            Ah[1] = a[2048 + ko];
            Ah[2] = a[ko + 4];        Ah[3] = a[2048 + ko + 4];
            Al[0] = a[128 + ko];      Al[1] = a[2176 + ko];
            Al[2] = a[128 + ko + 4];  Al[3] = a[2176 + ko + 4];
            mma16(acc1[i][0], Ah, bh[0]);
            mma16(acc2[i][0], Ah, bl[0]);
            mma16(acc2[i][0], Al, bh[0]);
            mma16(acc1[i][1], Ah, bh[1]);
            mma16(acc2[i][1], Ah, bl[1]);
            mma16(acc2[i][1], Al, bh[1]);
        }
        if (kc < 15) {
#pragma unroll
            for (int j = 0; j < 2; j++) {
                bh[j][0] = nbh[j][0]; bh[j][1] = nbh[j][1];
                bl[j][0] = nbl[j][0]; bl[j][1] = nbl[j][1];
            }
        }
        ko += 8;
    }

    // epilogue: combine split accumulators + fused BN, fragment stores
#pragma unroll
    for (int i = 0; i < 4; i++) {
        int r0 = m0 + wm * 64 + i * 16 + g;
        int r1 = r0 + 8;
        float sc0 = g_scale[mt][r0], sh0 = g_shift[mt][r0];
        float sc1 = g_scale[mt][r1], sh1 = g_shift[mt][r1];
#pragma unroll
        for (int j = 0; j < 2; j++) {
            int ncol = n0 + (wn * 2 + j) * 8 + c * 2;
            float v0 = acc1[i][j][0] + acc2[i][j][0] * LO_INV;
            float v1 = acc1[i][j][1] + acc2[i][j][1] * LO_INV;
            float v2 = acc1[i][j][2] + acc2[i][j][2] * LO_INV;
            float v3 = acc1[i][j][3] + acc2[i][j][3] * LO_INV;
            *reinterpret_cast<float2*>(out + (size_t)r0 * NF + ncol) =
                make_float2(v0 * sc0 + sh0, v1 * sc0 + sh0);
            *reinterpret_cast<float2*>(out + (size_t)r1 * NF + ncol) =
                make_float2(v2 * sc1 + sh1, v3 * sc1 + sh1);
        }
    }
}

// ---------------- K3: triple LIF + kv_local ----------------
__global__ void k_lif3() {
    int e = blockIdx.x * 256 + threadIdx.x;
    if (e >= PLANE) return;
    int c = e / 800;
    int nb = e - c * 800;
    int bse = c * NF + nb;
    float vq = 0.f, vk = 0.f, vv = 0.f;
    for (int t = 0; t < T_DIM; t++) {
        int off = bse + t * 800;
        float aq = __ldcs(g_yq + off);
        float ak = __ldcs(g_yk + off);
        float av = __ldcs(g_yv + off);
        float q = vq + (aq - vq) * 0.5f;
        float sq = (q >= 1.f) ? 1.f : 0.f;
        vq = q * (1.f - sq);
        float k = vk + (ak - vk) * 0.5f;
        float sk = (k >= 1.f) ? 1.f : 0.f;
        vk = k * (1.f - sk);
        float v = vv + (av - vv) * 0.5f;
        float sv = (v >= 1.f) ? 1.f : 0.f;
        vv = v * (1.f - sv);
        g_qs[off] = sq;
        g_kvl[off] = sk * sv;
    }
}

// ---------------- K4: topo routing + LIF(0.5) + SSRE -> split attn ----------------
__global__ void __launch_bounds__(224) k_topo_ssre() {
    int bid = blockIdx.x;
    int b = bid >> 5;
    int rest = bid & 31;
    int h = rest >> 2;
    int dg = rest & 3;
    int tid = threadIdx.x;

    __shared__ float topo_s[V_DIM * V_DIM];
    __shared__ float kvb[2][200];
    for (int i = tid; i < V_DIM * V_DIM; i += 224) topo_s[i] = g_topo[h][i];

    bool active = tid < 200;
    int d_local = tid / V_DIM;
    int i = tid - d_local * V_DIM;
    int c = h * HD_DIM + dg * 8 + d_local;
    int pbase = c * NF + b * V_DIM + i;
    unsigned short* QH = reinterpret_cast<unsigned short*>(g_qsp);

    float dec = 0.f;
    if (active) dec = g_decay[h * HD_DIM + dg * 8 + d_local];
    float omd = 1.f - dec;
    float vm = 0.f, S = 0.f;

    if (active) kvb[0][tid] = g_kvl[pbase];

    for (int t = 0; t < T_DIM; t++) {
        __syncthreads();
        int cur = t & 1;
        if (t + 1 < T_DIM && active) kvb[cur ^ 1][tid] = g_kvl[pbase + (t + 1) * 800];
        if (active) {
            const float* kr = &kvb[cur][d_local * V_DIM];
            const float* tr = &topo_s[i * V_DIM];
            float sp = 0.f, sp2 = 0.f;
#pragma unroll
            for (int j = 0; j < 24; j += 2) {
                sp += tr[j] * kr[j];
                sp2 += tr[j + 1] * kr[j + 1];
            }
            sp += tr[24] * kr[24] + sp2;
            vm = vm + (sp - vm) * 0.5f;
            float sk = (vm >= 0.5f) ? 1.f : 0.f;
            vm *= (1.f - sk);
            S = dec * S + omd * sk;
            int off = pbase + t * 800;
            float a = g_qs[off] * S;
            uint32_t u = pack_split(a);
            size_t n = (size_t)t * 800 + b * V_DIM + i;
            QH[n * 512 + c] = (unsigned short)(u & 0xFFFF);
            QH[n * 512 + 256 + c] = (unsigned short)(u >> 16);
        }
    }
}

// ---------------- K6: final LIF(0.5) + identity ----------------
__global__ void k_final(const float* __restrict__ x, float* __restrict__ out) {
    int e = blockIdx.x * 256 + threadIdx.x;
    if (e >= PLANE) return;
    int c = e / 800;
    int nb = e - c * 800;
    int b = nb / V_DIM;
    int v = nb - b * V_DIM;
    int ybase = c * NF + nb;
    int xoff = b * (C_DIM * V_DIM) + c * V_DIM + v;
    float vm = 0.f;
    for (int t = 0; t < T_DIM; t++) {
        float y = __ldcs(g_yq + ybase + t * 800);
        float vv = vm + (y - vm) * 0.5f;
        float s = (vv >= 0.5f) ? 1.f : 0.f;
        vm = vv * (1.f - s);
        int xo = t * PLANE + xoff;
        out[xo] = s + x[xo];
    }
}

// ---------------- launch ----------------
extern "C" void kernel_launch(void* const* d_in, const int* in_sizes, int n_in,
                              void* d_out, int out_size) {
    const float* x = (const float*)d_in[0];
    const float* alpha = (const float*)d_in[1];

    PrepArgs p;
    p.w[0] = (const float*)d_in[2];
    p.w[1] = (const float*)d_in[3];
    p.w[2] = (const float*)d_in[4];

    if (in_sizes[5] == 625) {
        p.base    = (const float*)d_in[5];
        p.learned = (const float*)d_in[6];
        p.sdw     = (const float*)d_in[7];
        p.w[3]    = (const float*)d_in[8];
        p.projb   = (const float*)d_in[9];
        for (int m = 0; m < 4; m++) {
            int o = 10 + m * 4;
            p.gamma[m] = (const float*)d_in[o + 0];
            p.beta[m]  = (const float*)d_in[o + 1];
            p.mean[m]  = (const float*)d_in[o + 2];
            p.var[m]   = (const float*)d_in[o + 3];
        }
    } else {
        for (int m = 0; m < 3; m++) {
            int o = 5 + m * 4;
            p.gamma[m] = (const float*)d_in[o + 0];
            p.beta[m]  = (const float*)d_in[o + 1];
            p.mean[m]  = (const float*)d_in[o + 2];
            p.var[m]   = (const float*)d_in[o + 3];
        }
        p.base    = (const float*)d_in[17];
        p.learned = (const float*)d_in[18];
        p.sdw     = (const float*)d_in[19];
        p.w[3]    = (const float*)d_in[20];
        p.projb   = (const float*)d_in[21];
        p.gamma[3] = (const float*)d_in[22];
        p.beta[3]  = (const float*)d_in[23];
        p.mean[3]  = (const float*)d_in[24];
        p.var[3]   = (const float*)d_in[25];
    }

    float* out = (float*)d_out;

    k_prep<<<6, 256>>>(p);
    k_trans<<<T_DIM * B_DIM, 256>>>(x, alpha);
    k_gemm_mma<<<dim3(NF / BN, C_DIM / BM, 3), GTHREADS>>>(0);
    k_lif3<<<(PLANE + 255) / 256, 256>>>();
    k_topo_ssre<<<B_DIM * H_DIM * 4, 224>>>();
    k_gemm_mma<<<dim3(NF / BN, C_DIM / BM, 1), GTHREADS>>>(1);
    k_final<<<(PLANE + 255) / 256, 256>>>(x, out);
}

// round 11
// speedup vs baseline: 1.5159x; 1.5159x over previous
#include <cuda_runtime.h>
#include <cuda_fp16.h>
#include <math.h>
#include <stdint.h>

typedef unsigned long long ull;

// ---------------- problem constants ----------------
#define T_DIM 64
#define B_DIM 32
#define C_DIM 256
#define V_DIM 25
#define H_DIM 8
#define HD_DIM 32
#define PLANE  (B_DIM * C_DIM * V_DIM)    // 204800
#define TOT    (T_DIM * PLANE)            // 13107200
#define NF     (T_DIM * B_DIM * V_DIM)    // 51200  (GEMM N)

// ---------------- device scratch ----------------
// split planes: row r = 128 u32 words; word w = f16x2 of elements k=2w,2w+1
// (low half = 2w). hi plane and lo plane separate. lo is residual * 1024.
__device__ __align__(16) uint32_t g_whi[4][C_DIM * 128];
__device__ __align__(16) uint32_t g_wlo[4][C_DIM * 128];
__device__ __align__(16) uint32_t g_qhi[(size_t)NF * 128];  // qkv_in; later attn
__device__ __align__(16) uint32_t g_qlo[(size_t)NF * 128];
__device__ __align__(16) uint32_t g_xhi[(size_t)NF * 128];
__device__ __align__(16) uint32_t g_xlo[(size_t)NF * 128];

// fp32 tensors, [c][n] layout (addr = c*NF + t*800 + b*25 + v)
__device__ __align__(16) float g_yq[TOT];    // q bn-conv out; later proj bn-conv out
__device__ __align__(16) float g_yk[TOT];
__device__ __align__(16) float g_yv[TOT];
__device__ __align__(16) float g_qs[TOT];    // q spikes
__device__ __align__(16) float g_kvl[TOT];   // k_s * v_s

__device__ float g_scale[4][C_DIM];
__device__ float g_shift[4][C_DIM];
__device__ float g_topo[H_DIM][V_DIM * V_DIM];
__device__ float g_decay[C_DIM];

// ---------------- helpers ----------------
#define LO_SCALE 1024.0f
#define LO_INV   (1.0f / 1024.0f)

// per-element split packed as (hi, lo) halves in one u32 (hi = low half)
__device__ __forceinline__ uint32_t pack_split(float x) {
    __half h = __float2half_rn(x);
    float r = (x - __half2float(h)) * LO_SCALE;
    __half l = __float2half_rn(r);
    __half2 p = __halves2half2(h, l);
    return *reinterpret_cast<uint32_t*>(&p);
}
// pair split: hi word = (h(a),h(b)), lo word = (l(a),l(b))
__device__ __forceinline__ void split2(float a, float b, uint32_t& hi, uint32_t& lo) {
    __half ha = __float2half_rn(a), hb = __float2half_rn(b);
    float ra = (a - __half2float(ha)) * LO_SCALE;
    float rb = (b - __half2float(hb)) * LO_SCALE;
    __half2 hh = __halves2half2(ha, hb);
    __half2 ll = __halves2half2(__float2half_rn(ra), __float2half_rn(rb));
    hi = *reinterpret_cast<uint32_t*>(&hh);
    lo = *reinterpret_cast<uint32_t*>(&ll);
}

// m16n8k16 f16 mma
__device__ __forceinline__ void mma16(float* c, const uint32_t* a, const uint32_t* b) {
    asm volatile(
        "mma.sync.aligned.m16n8k16.row.col.f32.f16.f16.f32 "
        "{%0,%1,%2,%3}, {%4,%5,%6,%7}, {%8,%9}, {%0,%1,%2,%3};"
        : "+f"(c[0]), "+f"(c[1]), "+f"(c[2]), "+f"(c[3])
        : "r"(a[0]), "r"(a[1]), "r"(a[2]), "r"(a[3]), "r"(b[0]), "r"(b[1]));
}

// ---------------- K0: prep ----------------
struct PrepArgs {
    const float* w[4];
    const float* gamma[4];
    const float* beta[4];
    const float* mean[4];
    const float* var[4];
    const float* projb;
    const float* base;
    const float* learned;
    const float* sdw;
};

__global__ void k_prep(PrepArgs p) {
    int blk = blockIdx.x, tid = threadIdx.x;
    if (blk < 4) {
        const float* w = p.w[blk];
        for (int idx = tid; idx < C_DIM * 128; idx += 256) {
            int m = idx >> 7, wd = idx & 127;
            uint32_t hi, lo;
            split2(w[m * C_DIM + 2 * wd], w[m * C_DIM + 2 * wd + 1], hi, lo);
            g_whi[blk][m * 128 + wd] = hi;
            g_wlo[blk][m * 128 + wd] = lo;
        }
        float sc = p.gamma[blk][tid] * rsqrtf(p.var[blk][tid] + 1e-5f);
        float sh = p.beta[blk][tid] - p.mean[blk][tid] * sc;
        if (blk == 3) sh += p.projb[tid] * sc;
        g_scale[blk][tid] = sc;
        g_shift[blk][tid] = sh;
    } else if (blk == 4) {
        if (tid < H_DIM * V_DIM) {
            int h = tid / V_DIM, i = tid - h * V_DIM;
            float l[V_DIM];
            float mx = -1e30f;
            for (int j = 0; j < V_DIM; j++) {
                l[j] = p.base[i * V_DIM + j] + 0.5f * p.learned[(h * V_DIM + i) * V_DIM + j];
                mx = fmaxf(mx, l[j]);
            }
            float sum = 0.f;
            for (int j = 0; j < V_DIM; j++) { l[j] = expf(l[j] - mx); sum += l[j]; }
            float inv = 1.f / sum;
            for (int j = 0; j < V_DIM; j++) g_topo[h][i * V_DIM + j] = l[j] * inv;
        }
    } else {
        float w = p.sdw[tid];
        float sg = 1.f / (1.f + expf(-w));
        g_decay[tid] = fminf(0.99f, fmaxf(0.01f, sg));
    }
}

// ---------------- K1: transpose + split x and qkv_in ----------------
__global__ void k_trans(const float* __restrict__ x, const float* __restrict__ alpha) {
    __shared__ uint32_t sx[C_DIM * V_DIM];   // per-element packed (hi,lo), [c][v]
    __shared__ float alp[C_DIM];
    int tid = threadIdx.x;
    alp[tid] = alpha[tid];
    __syncthreads();

    int t = blockIdx.x >> 5;
    int b = blockIdx.x & 31;
    const float* xin = x + (size_t)t * PLANE + b * (C_DIM * V_DIM);
    const float* xpr = xin - PLANE;
    int nbase = t * 800 + b * V_DIM;

    // pass 1: x
    for (int idx = tid; idx < C_DIM * V_DIM; idx += 256)
        sx[idx] = pack_split(xin[idx]);
    __syncthreads();
    for (int odx = tid; odx < V_DIM * 128; odx += 256) {
        int v = odx >> 7, wd = odx & 127;
        uint32_t u0 = sx[(2 * wd) * V_DIM + v];
        uint32_t u1 = sx[(2 * wd + 1) * V_DIM + v];
        size_t n = nbase + v;
        g_xhi[n * 128 + wd] = (u0 & 0xFFFFu) | (u1 << 16);
        g_xlo[n * 128 + wd] = (u0 >> 16) | (u1 & 0xFFFF0000u);
    }
    __syncthreads();

    // pass 2: qkv_in = a*|dx| + (1-a)*x
    for (int idx = tid; idx < C_DIM * V_DIM; idx += 256) {
        int c = idx / V_DIM;
        float xv = xin[idx];
        float g = (t == 0) ? 0.f : fabsf(xv - xpr[idx]);
        float a = alp[c];
        sx[idx] = pack_split(a * g + (1.f - a) * xv);
    }
    __syncthreads();
    for (int odx = tid; odx < V_DIM * 128; odx += 256) {
        int v = odx >> 7, wd = odx & 127;
        uint32_t u0 = sx[(2 * wd) * V_DIM + v];
        uint32_t u1 = sx[(2 * wd + 1) * V_DIM + v];
        size_t n = nbase + v;
        g_qhi[n * 128 + wd] = (u0 & 0xFFFFu) | (u1 << 16);
        g_qlo[n * 128 + wd] = (u0 >> 16) | (u1 & 0xFFFF0000u);
    }
}

// ---------------- K2/K5: fp16x3 mma.sync GEMM, pre-split operands ----------------
// Block tile 128x64, BK=16, 256 threads (8 warps), warp tile 64x16, 2 CTA/SM.
#define BM 128
#define BN 64
#define GTHREADS 256
// u32 word offsets inside one buffer (3072 words = 12 KB)
#define AH_OFF 0
#define AL_OFF 1024
#define BH_OFF 2048
#define BL_OFF 2560
#define BUF_WORDS 3072
#define GSMEM_BYTES (2 * BUF_WORDS * 4)

__device__ __forceinline__ void stage_load(const uint32_t* __restrict__ Whi, const uint32_t* __restrict__ Wlo,
                                           const uint32_t* __restrict__ Bhi, const uint32_t* __restrict__ Blo,
                                           int kc, int m0, int n0, int tid,
                                           uint32_t* ah, uint32_t* al, uint32_t* bh, uint32_t* bl) {
    int lane = tid & 31, rest = tid >> 5;
    int g = lane >> 2, c = lane & 3;
    int w = kc * 8 + c;
    {   // A fragment slot: rows (m0+rest*16+g), +8; words w, w+4
        size_t r = (size_t)(m0 + rest * 16 + g) * 128;
        ah[0] = Whi[r + w];        ah[1] = Whi[r + 1024 + w];
        ah[2] = Whi[r + w + 4];    ah[3] = Whi[r + 1024 + w + 4];
        al[0] = Wlo[r + w];        al[1] = Wlo[r + 1024 + w];
        al[2] = Wlo[r + w + 4];    al[3] = Wlo[r + 1024 + w + 4];
    }
    {   // B fragment slot: col n, words w, w+4
        size_t n = (size_t)(n0 + rest * 8 + g) * 128;
        bh[0] = Bhi[n + w]; bh[1] = Bhi[n + w + 4];
        bl[0] = Blo[n + w]; bl[1] = Blo[n + w + 4];
    }
}

__device__ __forceinline__ void stage_store(uint32_t* sb, int tid,
                                            const uint32_t* ah, const uint32_t* al,
                                            const uint32_t* bh, const uint32_t* bl) {
    *reinterpret_cast<uint4*>(sb + AH_OFF + tid * 4) = make_uint4(ah[0], ah[1], ah[2], ah[3]);
    *reinterpret_cast<uint4*>(sb + AL_OFF + tid * 4) = make_uint4(al[0], al[1], al[2], al[3]);
    *reinterpret_cast<uint2*>(sb + BH_OFF + tid * 2) = make_uint2(bh[0], bh[1]);
    *reinterpret_cast<uint2*>(sb + BL_OFF + tid * 2) = make_uint2(bl[0], bl[1]);
}

__global__ void __launch_bounds__(GTHREADS, 2) k_gemm_mma(int pass) {
    extern __shared__ uint32_t sm32[];
    int mt;
    const uint32_t* Bhi;
    const uint32_t* Blo;
    float* out;
    if (pass == 0) {
        mt = blockIdx.z;
        if (mt == 2) { Bhi = g_xhi; Blo = g_xlo; }
        else         { Bhi = g_qhi; Blo = g_qlo; }
        out = (mt == 0) ? g_yq : (mt == 1) ? g_yk : g_yv;
    } else {
        mt = 3;
        Bhi = g_qhi; Blo = g_qlo;
        out = g_yq;
    }
    const uint32_t* Whi = g_whi[mt];
    const uint32_t* Wlo = g_wlo[mt];
    int m0 = blockIdx.y * BM;
    int n0 = blockIdx.x * BN;
    int tid = threadIdx.x;
    int lane = tid & 31, wid = tid >> 5;
    int wm = wid >> 2;   // 0..1 -> 64 rows
    int wn = wid & 3;    // 0..3 -> 16 cols (2 nf)

    float acc1[4][2][4], acc2[4][2][4];
#pragma unroll
    for (int i = 0; i < 4; i++)
#pragma unroll
        for (int j = 0; j < 2; j++)
#pragma unroll
            for (int r = 0; r < 4; r++) { acc1[i][j][r] = 0.f; acc2[i][j][r] = 0.f; }

    uint32_t ah[4], al[4], bh[2], bl[2];
    stage_load(Whi, Wlo, Bhi, Blo, 0, m0, n0, tid, ah, al, bh, bl);
    stage_store(sm32, tid, ah, al, bh, bl);
    __syncthreads();

    for (int kc = 0; kc < 16; kc++) {
        uint32_t* sb = sm32 + (kc & 1) * BUF_WORDS;
        bool more = (kc + 1 < 16);
        if (more) stage_load(Whi, Wlo, Bhi, Blo, kc + 1, m0, n0, tid, ah, al, bh, bl);

        uint32_t Bh[2][2], Bl[2][2];
#pragma unroll
        for (int j = 0; j < 2; j++) {
            int fi = ((wn * 2 + j) * 32 + lane) * 2;
            uint2 b2h = *reinterpret_cast<const uint2*>(sb + BH_OFF + fi);
            uint2 b2l = *reinterpret_cast<const uint2*>(sb + BL_OFF + fi);
            Bh[j][0] = b2h.x; Bh[j][1] = b2h.y;
            Bl[j][0] = b2l.x; Bl[j][1] = b2l.y;
        }
#pragma unroll
        for (int i = 0; i < 4; i++) {
            int fi = ((wm * 4 + i) * 32 + lane) * 4;
            uint4 ah4 = *reinterpret_cast<const uint4*>(sb + AH_OFF + fi);
            uint4 al4 = *reinterpret_cast<const uint4*>(sb + AL_OFF + fi);
            uint32_t Ah[4] = {ah4.x, ah4.y, ah4.z, ah4.w};
            uint32_t Al[4] = {al4.x, al4.y, al4.z, al4.w};
#pragma unroll
            for (int j = 0; j < 2; j++) {
                mma16(acc1[i][j], Ah, Bh[j]);
                mma16(acc2[i][j], Ah, Bl[j]);
                mma16(acc2[i][j], Al, Bh[j]);
            }
        }
        if (more) stage_store(sm32 + ((kc + 1) & 1) * BUF_WORDS, tid, ah, al, bh, bl);
        __syncthreads();
    }

    // epilogue: combine split accumulators + fused BN, fragment stores
    int g = lane >> 2, c = lane & 3;
#pragma unroll
    for (int i = 0; i < 4; i++) {
        int r0 = m0 + wm * 64 + i * 16 + g;
        int r1 = r0 + 8;
        float sc0 = g_scale[mt][r0], sh0 = g_shift[mt][r0];
        float sc1 = g_scale[mt][r1], sh1 = g_shift[mt][r1];
#pragma unroll
        for (int j = 0; j < 2; j++) {
            int ncol = n0 + (wn * 2 + j) * 8 + c * 2;
            float v0 = acc1[i][j][0] + acc2[i][j][0] * LO_INV;
            float v1 = acc1[i][j][1] + acc2[i][j][1] * LO_INV;
            float v2 = acc1[i][j][2] + acc2[i][j][2] * LO_INV;
            float v3 = acc1[i][j][3] + acc2[i][j][3] * LO_INV;
            *reinterpret_cast<float2*>(out + (size_t)r0 * NF + ncol) =
                make_float2(v0 * sc0 + sh0, v1 * sc0 + sh0);
            *reinterpret_cast<float2*>(out + (size_t)r1 * NF + ncol) =
                make_float2(v2 * sc1 + sh1, v3 * sc1 + sh1);
        }
    }
}

// ---------------- K3: triple LIF + kv_local ----------------
__global__ void k_lif3() {
    int e = blockIdx.x * 256 + threadIdx.x;
    if (e >= PLANE) return;
    int c = e / 800;
    int nb = e - c * 800;
    int bse = c * NF + nb;
    float vq = 0.f, vk = 0.f, vv = 0.f;
    for (int t = 0; t < T_DIM; t++) {
        int off = bse + t * 800;
        float aq = __ldcs(g_yq + off);
        float ak = __ldcs(g_yk + off);
        float av = __ldcs(g_yv + off);
        float q = vq + (aq - vq) * 0.5f;
        float sq = (q >= 1.f) ? 1.f : 0.f;
        vq = q * (1.f - sq);
        float k = vk + (ak - vk) * 0.5f;
        float sk = (k >= 1.f) ? 1.f : 0.f;
        vk = k * (1.f - sk);
        float v = vv + (av - vv) * 0.5f;
        float sv = (v >= 1.f) ? 1.f : 0.f;
        vv = v * (1.f - sv);
        g_qs[off] = sq;
        g_kvl[off] = sk * sv;
    }
}

// ---------------- K4: topo routing + LIF(0.5) + SSRE -> split attn ----------------
__global__ void __launch_bounds__(224) k_topo_ssre() {
    int bid = blockIdx.x;
    int b = bid >> 5;
    int rest = bid & 31;
    int h = rest >> 2;
    int dg = rest & 3;
    int tid = threadIdx.x;

    __shared__ float topo_s[V_DIM * V_DIM];
    __shared__ float kvb[2][200];
    for (int i = tid; i < V_DIM * V_DIM; i += 224) topo_s[i] = g_topo[h][i];

    bool active = tid < 200;
    int d_local = tid / V_DIM;
    int i = tid - d_local * V_DIM;
    int c = h * HD_DIM + dg * 8 + d_local;
    int pbase = c * NF + b * V_DIM + i;
    unsigned short* QHI = reinterpret_cast<unsigned short*>(g_qhi);
    unsigned short* QLO = reinterpret_cast<unsigned short*>(g_qlo);

    float dec = 0.f;
    if (active) dec = g_decay[h * HD_DIM + dg * 8 + d_local];
    float omd = 1.f - dec;
    float vm = 0.f, S = 0.f;

    if (active) kvb[0][tid] = g_kvl[pbase];

    for (int t = 0; t < T_DIM; t++) {
        __syncthreads();
        int cur = t & 1;
        if (t + 1 < T_DIM && active) kvb[cur ^ 1][tid] = g_kvl[pbase + (t + 1) * 800];
        if (active) {
            const float* kr = &kvb[cur][d_local * V_DIM];
            const float* tr = &topo_s[i * V_DIM];
            float sp = 0.f, sp2 = 0.f;
#pragma unroll
            for (int j = 0; j < 24; j += 2) {
                sp += tr[j] * kr[j];
                sp2 += tr[j + 1] * kr[j + 1];
            }
            sp += tr[24] * kr[24] + sp2;
            vm = vm + (sp - vm) * 0.5f;
            float sk = (vm >= 0.5f) ? 1.f : 0.f;
            vm *= (1.f - sk);
            S = dec * S + omd * sk;
            int off = pbase + t * 800;
            float a = g_qs[off] * S;
            uint32_t u = pack_split(a);
            size_t n = (size_t)t * 800 + b * V_DIM + i;
            QHI[n * 256 + c] = (unsigned short)(u & 0xFFFF);
            QLO[n * 256 + c] = (unsigned short)(u >> 16);
        }
    }
}

// ---------------- K6: final LIF(0.5) + identity ----------------
__global__ void k_final(const float* __restrict__ x, float* __restrict__ out) {
    int e = blockIdx.x * 256 + threadIdx.x;
    if (e >= PLANE) return;
    int c = e / 800;
    int nb = e - c * 800;
    int b = nb / V_DIM;
    int v = nb - b * V_DIM;
    int ybase = c * NF + nb;
    int xoff = b * (C_DIM * V_DIM) + c * V_DIM + v;
    float vm = 0.f;
    for (int t = 0; t < T_DIM; t++) {
        float y = __ldcs(g_yq + ybase + t * 800);
        float vv = vm + (y - vm) * 0.5f;
        float s = (vv >= 0.5f) ? 1.f : 0.f;
        vm = vv * (1.f - s);
        int xo = t * PLANE + xoff;
        out[xo] = s + x[xo];
    }
}

// ---------------- launch ----------------
extern "C" void kernel_launch(void* const* d_in, const int* in_sizes, int n_in,
                              void* d_out, int out_size) {
    const float* x = (const float*)d_in[0];
    const float* alpha = (const float*)d_in[1];

    PrepArgs p;
    p.w[0] = (const float*)d_in[2];
    p.w[1] = (const float*)d_in[3];
    p.w[2] = (const float*)d_in[4];

    if (in_sizes[5] == 625) {
        p.base    = (const float*)d_in[5];
        p.learned = (const float*)d_in[6];
        p.sdw     = (const float*)d_in[7];
        p.w[3]    = (const float*)d_in[8];
        p.projb   = (const float*)d_in[9];
        for (int m = 0; m < 4; m++) {
            int o = 10 + m * 4;
            p.gamma[m] = (const float*)d_in[o + 0];
            p.beta[m]  = (const float*)d_in[o + 1];
            p.mean[m]  = (const float*)d_in[o + 2];
            p.var[m]   = (const float*)d_in[o + 3];
        }
    } else {
        for (int m = 0; m < 3; m++) {
            int o = 5 + m * 4;
            p.gamma[m] = (const float*)d_in[o + 0];
            p.beta[m]  = (const float*)d_in[o + 1];
            p.mean[m]  = (const float*)d_in[o + 2];
            p.var[m]   = (const float*)d_in[o + 3];
        }
        p.base    = (const float*)d_in[17];
        p.learned = (const float*)d_in[18];
        p.sdw     = (const float*)d_in[19];
        p.w[3]    = (const float*)d_in[20];
        p.projb   = (const float*)d_in[21];
        p.gamma[3] = (const float*)d_in[22];
        p.beta[3]  = (const float*)d_in[23];
        p.mean[3]  = (const float*)d_in[24];
        p.var[3]   = (const float*)d_in[25];
    }

    float* out = (float*)d_out;

    cudaFuncSetAttribute(k_gemm_mma, cudaFuncAttributeMaxDynamicSharedMemorySize, GSMEM_BYTES);

    k_prep<<<6, 256>>>(p);
    k_trans<<<T_DIM * B_DIM, 256>>>(x, alpha);
    k_gemm_mma<<<dim3(NF / BN, C_DIM / BM, 3), GTHREADS, GSMEM_BYTES>>>(0);
    k_lif3<<<(PLANE + 255) / 256, 256>>>();
    k_topo_ssre<<<B_DIM * H_DIM * 4, 224>>>();
    k_gemm_mma<<<dim3(NF / BN, C_DIM / BM, 1), GTHREADS, GSMEM_BYTES>>>(1);
    k_final<<<(PLANE + 255) / 256, 256>>>(x, out);
}

// round 12
// speedup vs baseline: 2.2923x; 1.5121x over previous
#include <cuda_runtime.h>
#include <cuda_fp16.h>
#include <math.h>
#include <stdint.h>

typedef unsigned long long ull;

// ---------------- problem constants ----------------
#define T_DIM 64
#define B_DIM 32
#define C_DIM 256
#define V_DIM 25
#define H_DIM 8
#define HD_DIM 32
#define PLANE  (B_DIM * C_DIM * V_DIM)    // 204800
#define TOT    (T_DIM * PLANE)            // 13107200
#define NF     (T_DIM * B_DIM * V_DIM)    // 51200  (GEMM N)

// ---------------- device scratch ----------------
// GEMM-adjacent layout: [c][t][b][v]  (addr = c*NF + t*800 + b*25 + v)
__device__ __align__(16) float g_qt[TOT];    // qkv_in transposed; later attn
__device__ __align__(16) float g_yq[TOT];    // q bn-conv out; later proj bn-conv out
__device__ __align__(16) float g_yk[TOT];
__device__ __align__(16) float g_yv[TOT];
__device__ __align__(16) float g_qs[TOT];    // q spikes
__device__ __align__(16) float g_kvl[TOT];   // k_s * v_s

__device__ float g_scale[4][C_DIM];
__device__ float g_shift[4][C_DIM];
__device__ float g_topo[H_DIM][V_DIM * V_DIM];
__device__ float g_decay[C_DIM];

// ---------------- helpers ----------------
#define LO_SCALE 1024.0f
#define LO_INV   (1.0f / 1024.0f)

// split pair (a,b) into packed f16x2 hi + scaled-residual lo
__device__ __forceinline__ void split_h2(float a, float b, uint32_t& h, uint32_t& l) {
    __half ha = __float2half_rn(a), hb = __float2half_rn(b);
    float ra = (a - __half2float(ha)) * LO_SCALE;
    float rb = (b - __half2float(hb)) * LO_SCALE;
    __half la = __float2half_rn(ra), lb = __float2half_rn(rb);
    __half2 hh = __halves2half2(ha, hb), ll = __halves2half2(la, lb);
    h = *reinterpret_cast<uint32_t*>(&hh);
    l = *reinterpret_cast<uint32_t*>(&ll);
}

// m16n8k16 f16 mma: acc(4 f32) += A(4x f16x2) x B(2x f16x2)
__device__ __forceinline__ void mma16(float* c, const uint32_t* a, const uint32_t* b) {
    asm volatile(
        "mma.sync.aligned.m16n8k16.row.col.f32.f16.f16.f32 "
        "{%0,%1,%2,%3}, {%4,%5,%6,%7}, {%8,%9}, {%0,%1,%2,%3};"
        : "+f"(c[0]), "+f"(c[1]), "+f"(c[2]), "+f"(c[3])
        : "r"(a[0]), "r"(a[1]), "r"(a[2]), "r"(a[3]), "r"(b[0]), "r"(b[1]));
}

// ---------------- K0: prep ----------------
struct PrepArgs {
    const float* w[4];
    const float* gamma[4];
    const float* beta[4];
    const float* mean[4];
    const float* var[4];
    const float* projb;
    const float* base;
    const float* learned;
    const float* sdw;
};

__global__ void k_prep(PrepArgs p) {
    int blk = blockIdx.x, tid = threadIdx.x;
    if (blk < 4) {
        float sc = p.gamma[blk][tid] * rsqrtf(p.var[blk][tid] + 1e-5f);
        float sh = p.beta[blk][tid] - p.mean[blk][tid] * sc;
        if (blk == 3) sh += p.projb[tid] * sc;
        g_scale[blk][tid] = sc;
        g_shift[blk][tid] = sh;
    } else if (blk == 4) {
        if (tid < H_DIM * V_DIM) {
            int h = tid / V_DIM, i = tid - h * V_DIM;
            float l[V_DIM];
            float mx = -1e30f;
            for (int j = 0; j < V_DIM; j++) {
                l[j] = p.base[i * V_DIM + j] + 0.5f * p.learned[(h * V_DIM + i) * V_DIM + j];
                mx = fmaxf(mx, l[j]);
            }
            float sum = 0.f;
            for (int j = 0; j < V_DIM; j++) { l[j] = expf(l[j] - mx); sum += l[j]; }
            float inv = 1.f / sum;
            for (int j = 0; j < V_DIM; j++) g_topo[h][i * V_DIM + j] = l[j] * inv;
        }
    } else {
        float w = p.sdw[tid];
        float sg = 1.f / (1.f + expf(-w));
        g_decay[tid] = fminf(0.99f, fmaxf(0.01f, sg));
    }
}

// ---------------- K1: transpose + qkv_in (qt only) ----------------
__global__ void k_trans(const float* __restrict__ x, const float* __restrict__ alpha) {
    __shared__ float alp[C_DIM];
    int tid = threadIdx.x;
    alp[tid] = alpha[tid];
    __syncthreads();

    int t = blockIdx.x >> 5;
    int b = blockIdx.x & 31;
    const float* xin = x + (size_t)t * PLANE + b * (C_DIM * V_DIM);
    const float* xpr = xin - PLANE;
    int nbase = t * 800 + b * V_DIM;

    for (int idx = tid; idx < C_DIM * V_DIM; idx += 256) {
        int c = idx / V_DIM;
        int v = idx - c * V_DIM;
        float xv = xin[idx];
        float g = (t == 0) ? 0.f : fabsf(xv - xpr[idx]);
        float a = alp[c];
        g_qt[c * NF + nbase + v] = a * g + (1.f - a) * xv;
    }
}

// ---------------- K2/K5: fp16x3 mma.sync GEMM + fused BN ----------------
// Block tile 128x64, BK=32 (two k16-MMA groups per chunk), 256 threads (8 warps),
// warp tile 64x16, dual accumulators (Markidis split), 2 CTA/SM.
#define BM 128
#define BN 64
#define BK 32
#define GTHREADS 256
// u32 word offsets inside one buffer (6144 words = 24 KB)
#define AH_OFF 0
#define AL_OFF 2048
#define BH_OFF 4096
#define BL_OFF 5120
#define BUF_WORDS 6144
#define GSMEM_BYTES (2 * BUF_WORDS * 4)

struct GemmArgs { const float* w0; const float* w1; const float* w2; const float* w3; const float* x; };

__device__ __forceinline__ void stage_load(const float* __restrict__ A, const float* __restrict__ Bptr,
                                           size_t Bbase, int bk, int strideK,
                                           int kc, int m0, int tid, float* ra, float* rb) {
#pragma unroll
    for (int kf = 0; kf < 2; kf++) {
        int k0 = kc * BK + kf * 16;
        {   // A: frag mf = tid>>5, lane = tid&31
            int lane = tid & 31, mf = tid >> 5;
            int g = lane >> 2, c = lane & 3;
            const float* ap = A + (size_t)(m0 + mf * 16 + g) * C_DIM + k0 + 2 * c;
            float2 p0 = *reinterpret_cast<const float2*>(ap);
            float2 p1 = *reinterpret_cast<const float2*>(ap + 8);
            float2 q0 = *reinterpret_cast<const float2*>(ap + 8 * C_DIM);
            float2 q1 = *reinterpret_cast<const float2*>(ap + 8 * C_DIM + 8);
            float* r = ra + kf * 8;
            r[0] = p0.x; r[1] = p0.y;
            r[2] = q0.x; r[3] = q0.y;
            r[4] = p1.x; r[5] = p1.y;
            r[6] = q1.x; r[7] = q1.y;
        }
        {   // B
            const float* bp = Bptr + Bbase + (size_t)(k0 + bk) * strideK;
            float* r = rb + kf * 4;
            r[0] = bp[0];
            r[1] = bp[strideK];
            r[2] = bp[8 * strideK];
            r[3] = bp[9 * strideK];
        }
    }
}

__device__ __forceinline__ void stage_store(uint32_t* sb, int tid, const float* ra, const float* rb) {
#pragma unroll
    for (int kf = 0; kf < 2; kf++) {
        const float* r = ra + kf * 8;
        uint32_t h[4], l[4];
        split_h2(r[0], r[1], h[0], l[0]);
        split_h2(r[2], r[3], h[1], l[1]);
        split_h2(r[4], r[5], h[2], l[2]);
        split_h2(r[6], r[7], h[3], l[3]);
        *reinterpret_cast<uint4*>(sb + AH_OFF + kf * 1024 + tid * 4) = make_uint4(h[0], h[1], h[2], h[3]);
        *reinterpret_cast<uint4*>(sb + AL_OFF + kf * 1024 + tid * 4) = make_uint4(l[0], l[1], l[2], l[3]);

        const float* q = rb + kf * 4;
        uint32_t bh0, bl0, bh1, bl1;
        split_h2(q[0], q[1], bh0, bl0);
        split_h2(q[2], q[3], bh1, bl1);
        *reinterpret_cast<uint2*>(sb + BH_OFF + kf * 512 + tid * 2) = make_uint2(bh0, bh1);
        *reinterpret_cast<uint2*>(sb + BL_OFF + kf * 512 + tid * 2) = make_uint2(bl0, bl1);
    }
}

__global__ void __launch_bounds__(GTHREADS, 2) k_gemm_mma(GemmArgs ga, int pass) {
    extern __shared__ uint32_t sm32[];
    int mt;
    const float* A;
    const float* Bptr;
    float* out;
    bool direct = false;
    if (pass == 0) {
        mt = blockIdx.z;
        A = (mt == 0) ? ga.w0 : (mt == 1) ? ga.w1 : ga.w2;
        if (mt == 2) { Bptr = ga.x; direct = true; }
        else Bptr = g_qt;
        out = (mt == 0) ? g_yq : (mt == 1) ? g_yk : g_yv;
    } else {
        mt = 3;
        A = ga.w3;
        Bptr = g_qt;
        out = g_yq;
    }
    int m0 = blockIdx.y * BM;
    int n0 = blockIdx.x * BN;
    int tid = threadIdx.x;
    int lane = tid & 31, wid = tid >> 5;
    int wm = wid >> 2;   // 0..1 -> 64 rows
    int wn = wid & 3;    // 0..3 -> 16 cols (2 nf)

    // per-thread B addressing: slot nf/g fixed; k varies per chunk
    size_t Bbase;
    int bk;
    int strideK = direct ? V_DIM : NF;
    {
        int lane2 = tid & 31, nf = tid >> 5;
        int g = lane2 >> 2, c = lane2 & 3;
        bk = 2 * c;                        // k rows 2c,2c+1,2c+8,2c+9
        int n = n0 + nf * 8 + g;
        if (direct) {
            int t = n / 800;
            int r = n - t * 800;
            int b = r / V_DIM;
            int v = r - b * V_DIM;
            Bbase = (size_t)t * PLANE + b * (C_DIM * V_DIM) + v;
        } else {
            Bbase = (size_t)n;
        }
    }

    float acc1[4][2][4], acc2[4][2][4];
#pragma unroll
    for (int i = 0; i < 4; i++)
#pragma unroll
        for (int j = 0; j < 2; j++)
#pragma unroll
            for (int r = 0; r < 4; r++) { acc1[i][j][r] = 0.f; acc2[i][j][r] = 0.f; }

    float ra[16], rb[8];
    stage_load(A, Bptr, Bbase, bk, strideK, 0, m0, tid, ra, rb);
    stage_store(sm32, tid, ra, rb);
    __syncthreads();

    for (int kc = 0; kc < C_DIM / BK; kc++) {
        uint32_t* sb = sm32 + (kc & 1) * BUF_WORDS;
        bool more = (kc + 1 < C_DIM / BK);
        if (more) stage_load(A, Bptr, Bbase, bk, strideK, kc + 1, m0, tid, ra, rb);

#pragma unroll
        for (int kf = 0; kf < 2; kf++) {
            uint32_t Bh[2][2], Bl[2][2];
#pragma unroll
            for (int j = 0; j < 2; j++) {
                int fi = kf * 512 + ((wn * 2 + j) * 32 + lane) * 2;
                uint2 bh = *reinterpret_cast<const uint2*>(sb + BH_OFF + fi);
                uint2 bl = *reinterpret_cast<const uint2*>(sb + BL_OFF + fi);
                Bh[j][0] = bh.x; Bh[j][1] = bh.y;
                Bl[j][0] = bl.x; Bl[j][1] = bl.y;
            }
#pragma unroll
            for (int i = 0; i < 4; i++) {
                int fi = kf * 1024 + ((wm * 4 + i) * 32 + lane) * 4;
                uint4 ah4 = *reinterpret_cast<const uint4*>(sb + AH_OFF + fi);
                uint4 al4 = *reinterpret_cast<const uint4*>(sb + AL_OFF + fi);
                uint32_t Ah[4] = {ah4.x, ah4.y, ah4.z, ah4.w};
                uint32_t Al[4] = {al4.x, al4.y, al4.z, al4.w};
#pragma unroll
                for (int j = 0; j < 2; j++) {
                    mma16(acc1[i][j], Ah, Bh[j]);
                    mma16(acc2[i][j], Ah, Bl[j]);
                    mma16(acc2[i][j], Al, Bh[j]);
                }
            }
        }
        if (more) stage_store(sm32 + ((kc + 1) & 1) * BUF_WORDS, tid, ra, rb);
        __syncthreads();
    }

    // epilogue: combine split accumulators + fused BN, fragment stores
    int g = lane >> 2, c = lane & 3;
#pragma unroll
    for (int i = 0; i < 4; i++) {
        int r0 = m0 + wm * 64 + i * 16 + g;
        int r1 = r0 + 8;
        float sc0 = g_scale[mt][r0], sh0 = g_shift[mt][r0];
        float sc1 = g_scale[mt][r1], sh1 = g_shift[mt][r1];
#pragma unroll
        for (int j = 0; j < 2; j++) {
            int ncol = n0 + (wn * 2 + j) * 8 + c * 2;
            float v0 = acc1[i][j][0] + acc2[i][j][0] * LO_INV;
            float v1 = acc1[i][j][1] + acc2[i][j][1] * LO_INV;
            float v2 = acc1[i][j][2] + acc2[i][j][2] * LO_INV;
            float v3 = acc1[i][j][3] + acc2[i][j][3] * LO_INV;
            *reinterpret_cast<float2*>(out + (size_t)r0 * NF + ncol) =
                make_float2(v0 * sc0 + sh0, v1 * sc0 + sh0);
            *reinterpret_cast<float2*>(out + (size_t)r1 * NF + ncol) =
                make_float2(v2 * sc1 + sh1, v3 * sc1 + sh1);
        }
    }
}

// ---------------- K3: triple LIF + kv_local ----------------
__global__ void k_lif3() {
    int e = blockIdx.x * 256 + threadIdx.x;
    if (e >= PLANE) return;
    int c = e / 800;
    int nb = e - c * 800;
    int bse = c * NF + nb;
    float vq = 0.f, vk = 0.f, vv = 0.f;
    for (int t = 0; t < T_DIM; t++) {
        int off = bse + t * 800;
        float aq = __ldcs(g_yq + off);
        float ak = __ldcs(g_yk + off);
        float av = __ldcs(g_yv + off);
        float q = vq + (aq - vq) * 0.5f;
        float sq = (q >= 1.f) ? 1.f : 0.f;
        vq = q * (1.f - sq);
        float k = vk + (ak - vk) * 0.5f;
        float sk = (k >= 1.f) ? 1.f : 0.f;
        vk = k * (1.f - sk);
        float v = vv + (av - vv) * 0.5f;
        float sv = (v >= 1.f) ? 1.f : 0.f;
        vv = v * (1.f - sv);
        g_qs[off] = sq;
        g_kvl[off] = sk * sv;
    }
}

// ---------------- K4: topo routing + LIF(0.5) + SSRE ----------------
__global__ void __launch_bounds__(224) k_topo_ssre() {
    int bid = blockIdx.x;
    int b = bid >> 5;
    int rest = bid & 31;
    int h = rest >> 2;
    int dg = rest & 3;
    int tid = threadIdx.x;

    __shared__ float topo_s[V_DIM * V_DIM];
    __shared__ float kvb[2][200];
    for (int i = tid; i < V_DIM * V_DIM; i += 224) topo_s[i] = g_topo[h][i];

    bool active = tid < 200;
    int d_local = tid / V_DIM;
    int i = tid - d_local * V_DIM;
    int c = h * HD_DIM + dg * 8 + d_local;
    int pbase = c * NF + b * V_DIM + i;

    float dec = 0.f;
    if (active) dec = g_decay[h * HD_DIM + dg * 8 + d_local];
    float omd = 1.f - dec;
    float vm = 0.f, S = 0.f;

    if (active) kvb[0][tid] = g_kvl[pbase];

    for (int t = 0; t < T_DIM; t++) {
        __syncthreads();
        int cur = t & 1;
        if (t + 1 < T_DIM && active) kvb[cur ^ 1][tid] = g_kvl[pbase + (t + 1) * 800];
        if (active) {
            const float* kr = &kvb[cur][d_local * V_DIM];
            const float* tr = &topo_s[i * V_DIM];
            float sp = 0.f, sp2 = 0.f;
#pragma unroll
            for (int j = 0; j < 24; j += 2) {
                sp += tr[j] * kr[j];
                sp2 += tr[j + 1] * kr[j + 1];
            }
            sp += tr[24] * kr[24] + sp2;
            vm = vm + (sp - vm) * 0.5f;
            float sk = (vm >= 0.5f) ? 1.f : 0.f;
            vm *= (1.f - sk);
            S = dec * S + omd * sk;
            int off = pbase + t * 800;
            g_qt[off] = g_qs[off] * S;
        }
    }
}

// ---------------- K6: final LIF(0.5) + identity ----------------
__global__ void k_final(const float* __restrict__ x, float* __restrict__ out) {
    int e = blockIdx.x * 256 + threadIdx.x;
    if (e >= PLANE) return;
    int c = e / 800;
    int nb = e - c * 800;
    int b = nb / V_DIM;
    int v = nb - b * V_DIM;
    int ybase = c * NF + nb;
    int xoff = b * (C_DIM * V_DIM) + c * V_DIM + v;
    float vm = 0.f;
    for (int t = 0; t < T_DIM; t++) {
        float y = __ldcs(g_yq + ybase + t * 800);
        float vv = vm + (y - vm) * 0.5f;
        float s = (vv >= 0.5f) ? 1.f : 0.f;
        vm = vv * (1.f - s);
        int xo = t * PLANE + xoff;
        out[xo] = s + x[xo];
    }
}

// ---------------- launch ----------------
extern "C" void kernel_launch(void* const* d_in, const int* in_sizes, int n_in,
                              void* d_out, int out_size) {
    const float* x = (const float*)d_in[0];
    const float* alpha = (const float*)d_in[1];

    PrepArgs p;
    p.w[0] = (const float*)d_in[2];
    p.w[1] = (const float*)d_in[3];
    p.w[2] = (const float*)d_in[4];

    if (in_sizes[5] == 625) {
        p.base    = (const float*)d_in[5];
        p.learned = (const float*)d_in[6];
        p.sdw     = (const float*)d_in[7];
        p.w[3]    = (const float*)d_in[8];
        p.projb   = (const float*)d_in[9];
        for (int m = 0; m < 4; m++) {
            int o = 10 + m * 4;
            p.gamma[m] = (const float*)d_in[o + 0];
            p.beta[m]  = (const float*)d_in[o + 1];
            p.mean[m]  = (const float*)d_in[o + 2];
            p.var[m]   = (const float*)d_in[o + 3];
        }
    } else {
        for (int m = 0; m < 3; m++) {
            int o = 5 + m * 4;
            p.gamma[m] = (const float*)d_in[o + 0];
            p.beta[m]  = (const float*)d_in[o + 1];
            p.mean[m]  = (const float*)d_in[o + 2];
            p.var[m]   = (const float*)d_in[o + 3];
        }
        p.base    = (const float*)d_in[17];
        p.learned = (const float*)d_in[18];
        p.sdw     = (const float*)d_in[19];
        p.w[3]    = (const float*)d_in[20];
        p.projb   = (const float*)d_in[21];
        p.gamma[3] = (const float*)d_in[22];
        p.beta[3]  = (const float*)d_in[23];
        p.mean[3]  = (const float*)d_in[24];
        p.var[3]   = (const float*)d_in[25];
    }

    float* out = (float*)d_out;

    cudaFuncSetAttribute(k_gemm_mma, cudaFuncAttributeMaxDynamicSharedMemorySize, GSMEM_BYTES);

    GemmArgs ga;
    ga.w0 = p.w[0]; ga.w1 = p.w[1]; ga.w2 = p.w[2]; ga.w3 = p.w[3]; ga.x = x;

    k_prep<<<6, 256>>>(p);
    k_trans<<<T_DIM * B_DIM, 256>>>(x, alpha);
    k_gemm_mma<<<dim3(NF / BN, C_DIM / BM, 3), GTHREADS, GSMEM_BYTES>>>(ga, 0);
    k_lif3<<<(PLANE + 255) / 256, 256>>>();
    k_topo_ssre<<<B_DIM * H_DIM * 4, 224>>>();
    k_gemm_mma<<<dim3(NF / BN, C_DIM / BM, 1), GTHREADS, GSMEM_BYTES>>>(ga, 1);
    k_final<<<(PLANE + 255) / 256, 256>>>(x, out);
}

// round 13
// speedup vs baseline: 2.5331x; 1.1051x over previous
#include <cuda_runtime.h>
#include <cuda_fp16.h>
#include <math.h>
#include <stdint.h>

typedef unsigned long long ull;

// ---------------- problem constants ----------------
#define T_DIM 64
#define B_DIM 32
#define C_DIM 256
#define V_DIM 25
#define H_DIM 8
#define HD_DIM 32
#define PLANE  (B_DIM * C_DIM * V_DIM)    // 204800
#define TOT    (T_DIM * PLANE)            // 13107200
#define NF     (T_DIM * B_DIM * V_DIM)    // 51200  (GEMM N)

// ---------------- device scratch ----------------
// GEMM-adjacent layout: [c][t][b][v]  (addr = c*NF + t*800 + b*25 + v)
__device__ __align__(16) float g_qt[TOT];    // qkv_in transposed; later attn
__device__ __align__(16) float g_yq[TOT];    // q bn-conv out; later proj bn-conv out
__device__ __align__(16) float g_yk[TOT];
__device__ __align__(16) float g_yv[TOT];
__device__ unsigned char g_qs8[TOT];         // q spikes (0/1)
__device__ unsigned char g_kvl8[TOT];        // k_s * v_s (0/1)

// pre-packed weight fragments: [k16 0..15][mf 0..15][lane 0..31][w 0..3]
__device__ __align__(16) uint32_t g_wpkhi[4][32768];
__device__ __align__(16) uint32_t g_wpklo[4][32768];

__device__ float g_scale[4][C_DIM];
__device__ float g_shift[4][C_DIM];
__device__ float g_topo[H_DIM][V_DIM * V_DIM];
__device__ float g_decay[C_DIM];

// ---------------- helpers ----------------
#define LO_SCALE 1024.0f
#define LO_INV   (1.0f / 1024.0f)

__device__ __forceinline__ void split_h2(float a, float b, uint32_t& h, uint32_t& l) {
    __half ha = __float2half_rn(a), hb = __float2half_rn(b);
    float ra = (a - __half2float(ha)) * LO_SCALE;
    float rb = (b - __half2float(hb)) * LO_SCALE;
    __half la = __float2half_rn(ra), lb = __float2half_rn(rb);
    __half2 hh = __halves2half2(ha, hb), ll = __halves2half2(la, lb);
    h = *reinterpret_cast<uint32_t*>(&hh);
    l = *reinterpret_cast<uint32_t*>(&ll);
}

__device__ __forceinline__ void mma16(float* c, const uint32_t* a, const uint32_t* b) {
    asm volatile(
        "mma.sync.aligned.m16n8k16.row.col.f32.f16.f16.f32 "
        "{%0,%1,%2,%3}, {%4,%5,%6,%7}, {%8,%9}, {%0,%1,%2,%3};"
        : "+f"(c[0]), "+f"(c[1]), "+f"(c[2]), "+f"(c[3])
        : "r"(a[0]), "r"(a[1]), "r"(a[2]), "r"(a[3]), "r"(b[0]), "r"(b[1]));
}

// ---------------- K0: prep ----------------
struct PrepArgs {
    const float* w[4];
    const float* gamma[4];
    const float* beta[4];
    const float* mean[4];
    const float* var[4];
    const float* projb;
    const float* base;
    const float* learned;
    const float* sdw;
};

__global__ void k_prep(PrepArgs p) {
    int blk = blockIdx.x, tid = threadIdx.x;
    if (blk < 4) {
        const float* w = p.w[blk];
        // pack weight fragments: idx -> (k16, mf, lane, w)
        for (int idx = tid; idx < 32768; idx += 256) {
            int k16 = idx >> 11;
            int rest = idx & 2047;
            int mf = rest >> 7;
            int r2 = rest & 127;
            int lane = r2 >> 2;
            int wq = r2 & 3;
            int g = lane >> 2, c = lane & 3;
            int row = mf * 16 + g + (wq & 1) * 8;
            int col = k16 * 16 + 2 * c + ((wq & 2) ? 8 : 0);
            uint32_t hi, lo;
            split_h2(w[row * C_DIM + col], w[row * C_DIM + col + 1], hi, lo);
            g_wpkhi[blk][idx] = hi;
            g_wpklo[blk][idx] = lo;
        }
        float sc = p.gamma[blk][tid] * rsqrtf(p.var[blk][tid] + 1e-5f);
        float sh = p.beta[blk][tid] - p.mean[blk][tid] * sc;
        if (blk == 3) sh += p.projb[tid] * sc;
        g_scale[blk][tid] = sc;
        g_shift[blk][tid] = sh;
    } else if (blk == 4) {
        if (tid < H_DIM * V_DIM) {
            int h = tid / V_DIM, i = tid - h * V_DIM;
            float l[V_DIM];
            float mx = -1e30f;
            for (int j = 0; j < V_DIM; j++) {
                l[j] = p.base[i * V_DIM + j] + 0.5f * p.learned[(h * V_DIM + i) * V_DIM + j];
                mx = fmaxf(mx, l[j]);
            }
            float sum = 0.f;
            for (int j = 0; j < V_DIM; j++) { l[j] = expf(l[j] - mx); sum += l[j]; }
            float inv = 1.f / sum;
            for (int j = 0; j < V_DIM; j++) g_topo[h][i * V_DIM + j] = l[j] * inv;
        }
    } else {
        float w = p.sdw[tid];
        float sg = 1.f / (1.f + expf(-w));
        g_decay[tid] = fminf(0.99f, fmaxf(0.01f, sg));
    }
}

// ---------------- K1: transpose + qkv_in (qt only) ----------------
__global__ void k_trans(const float* __restrict__ x, const float* __restrict__ alpha) {
    __shared__ float alp[C_DIM];
    int tid = threadIdx.x;
    alp[tid] = alpha[tid];
    __syncthreads();

    int t = blockIdx.x >> 5;
    int b = blockIdx.x & 31;
    const float* xin = x + (size_t)t * PLANE + b * (C_DIM * V_DIM);
    const float* xpr = xin - PLANE;
    int nbase = t * 800 + b * V_DIM;

    for (int idx = tid; idx < C_DIM * V_DIM; idx += 256) {
        int c = idx / V_DIM;
        int v = idx - c * V_DIM;
        float xv = xin[idx];
        float g = (t == 0) ? 0.f : fabsf(xv - xpr[idx]);
        float a = alp[c];
        g_qt[c * NF + nbase + v] = a * g + (1.f - a) * xv;
    }
}

// ---------------- K2/K5: fp16x3 mma.sync GEMM + fused BN ----------------
// Block tile 128x64, BK=32, 256 threads (8 warps), warp tile 64x16, 2 CTA/SM.
// A staged from pre-packed fragment planes (copy only); B split inline.
#define BM 128
#define BN 64
#define BK 32
#define GTHREADS 256
// u32 word offsets inside one buffer (6144 words = 24 KB)
#define AH_OFF 0
#define AL_OFF 2048
#define BH_OFF 4096
#define BL_OFF 5120
#define BUF_WORDS 6144
#define GSMEM_BYTES (2 * BUF_WORDS * 4)

struct GemmArgs { const float* x; };

__device__ __forceinline__ void stage_load(const uint32_t* __restrict__ Ahi, const uint32_t* __restrict__ Alo,
                                           const float* __restrict__ Bptr,
                                           size_t Bbase, int bk, int strideK,
                                           int kc, int yoff, int tid,
                                           uint4* ah4, uint4* al4, float* rb) {
#pragma unroll
    for (int kf = 0; kf < 2; kf++) {
        size_t base = ((size_t)((kc * 2 + kf) * 16 + yoff + (tid >> 5)) << 7) + (tid & 31) * 4;
        ah4[kf] = *reinterpret_cast<const uint4*>(Ahi + base);
        al4[kf] = *reinterpret_cast<const uint4*>(Alo + base);
        int k0 = kc * BK + kf * 16;
        const float* bp = Bptr + Bbase + (size_t)(k0 + bk) * strideK;
        float* r = rb + kf * 4;
        r[0] = bp[0];
        r[1] = bp[strideK];
        r[2] = bp[8 * strideK];
        r[3] = bp[9 * strideK];
    }
}

__device__ __forceinline__ void stage_store(uint32_t* sb, int tid,
                                            const uint4* ah4, const uint4* al4, const float* rb) {
#pragma unroll
    for (int kf = 0; kf < 2; kf++) {
        *reinterpret_cast<uint4*>(sb + AH_OFF + kf * 1024 + tid * 4) = ah4[kf];
        *reinterpret_cast<uint4*>(sb + AL_OFF + kf * 1024 + tid * 4) = al4[kf];
        const float* q = rb + kf * 4;
        uint32_t bh0, bl0, bh1, bl1;
        split_h2(q[0], q[1], bh0, bl0);
        split_h2(q[2], q[3], bh1, bl1);
        *reinterpret_cast<uint2*>(sb + BH_OFF + kf * 512 + tid * 2) = make_uint2(bh0, bh1);
        *reinterpret_cast<uint2*>(sb + BL_OFF + kf * 512 + tid * 2) = make_uint2(bl0, bl1);
    }
}

__global__ void __launch_bounds__(GTHREADS, 2) k_gemm_mma(GemmArgs ga, int pass) {
    extern __shared__ uint32_t sm32[];
    int mt;
    const float* Bptr;
    float* out;
    bool direct = false;
    if (pass == 0) {
        mt = blockIdx.z;
        if (mt == 2) { Bptr = ga.x; direct = true; }
        else Bptr = g_qt;
        out = (mt == 0) ? g_yq : (mt == 1) ? g_yk : g_yv;
    } else {
        mt = 3;
        Bptr = g_qt;
        out = g_yq;
    }
    const uint32_t* Ahi = g_wpkhi[mt];
    const uint32_t* Alo = g_wpklo[mt];
    int m0 = blockIdx.y * BM;
    int yoff = blockIdx.y * 8;
    int n0 = blockIdx.x * BN;
    int tid = threadIdx.x;
    int lane = tid & 31, wid = tid >> 5;
    int wm = wid >> 2;   // 0..1 -> 64 rows
    int wn = wid & 3;    // 0..3 -> 16 cols (2 nf)

    // per-thread B addressing: slot nf/g fixed; k varies per chunk
    size_t Bbase;
    int bk;
    int strideK = direct ? V_DIM : NF;
    {
        int lane2 = tid & 31, nf = tid >> 5;
        int g = lane2 >> 2, c = lane2 & 3;
        bk = 2 * c;
        int n = n0 + nf * 8 + g;
        if (direct) {
            int t = n / 800;
            int r = n - t * 800;
            int b = r / V_DIM;
            int v = r - b * V_DIM;
            Bbase = (size_t)t * PLANE + b * (C_DIM * V_DIM) + v;
        } else {
            Bbase = (size_t)n;
        }
    }

    float acc1[4][2][4], acc2[4][2][4];
#pragma unroll
    for (int i = 0; i < 4; i++)
#pragma unroll
        for (int j = 0; j < 2; j++)
#pragma unroll
            for (int r = 0; r < 4; r++) { acc1[i][j][r] = 0.f; acc2[i][j][r] = 0.f; }

    uint4 ah4[2], al4[2];
    float rb[8];
    stage_load(Ahi, Alo, Bptr, Bbase, bk, strideK, 0, yoff, tid, ah4, al4, rb);
    stage_store(sm32, tid, ah4, al4, rb);
    __syncthreads();

    for (int kc = 0; kc < C_DIM / BK; kc++) {
        uint32_t* sb = sm32 + (kc & 1) * BUF_WORDS;
        bool more = (kc + 1 < C_DIM / BK);
        if (more) stage_load(Ahi, Alo, Bptr, Bbase, bk, strideK, kc + 1, yoff, tid, ah4, al4, rb);

#pragma unroll
        for (int kf = 0; kf < 2; kf++) {
            uint32_t Bh[2][2], Bl[2][2];
#pragma unroll
            for (int j = 0; j < 2; j++) {
                int fi = kf * 512 + ((wn * 2 + j) * 32 + lane) * 2;
                uint2 bh = *reinterpret_cast<const uint2*>(sb + BH_OFF + fi);
                uint2 bl = *reinterpret_cast<const uint2*>(sb + BL_OFF + fi);
                Bh[j][0] = bh.x; Bh[j][1] = bh.y;
                Bl[j][0] = bl.x; Bl[j][1] = bl.y;
            }
#pragma unroll
            for (int i = 0; i < 4; i++) {
                int fi = kf * 1024 + ((wm * 4 + i) * 32 + lane) * 4;
                uint4 a4 = *reinterpret_cast<const uint4*>(sb + AH_OFF + fi);
                uint4 l4 = *reinterpret_cast<const uint4*>(sb + AL_OFF + fi);
                uint32_t Ah[4] = {a4.x, a4.y, a4.z, a4.w};
                uint32_t Al[4] = {l4.x, l4.y, l4.z, l4.w};
#pragma unroll
                for (int j = 0; j < 2; j++) {
                    mma16(acc1[i][j], Ah, Bh[j]);
                    mma16(acc2[i][j], Ah, Bl[j]);
                    mma16(acc2[i][j], Al, Bh[j]);
                }
            }
        }
        if (more) stage_store(sm32 + ((kc + 1) & 1) * BUF_WORDS, tid, ah4, al4, rb);
        __syncthreads();
    }

    // epilogue: combine split accumulators + fused BN, fragment stores
    int g = lane >> 2, c = lane & 3;
#pragma unroll
    for (int i = 0; i < 4; i++) {
        int r0 = m0 + wm * 64 + i * 16 + g;
        int r1 = r0 + 8;
        float sc0 = g_scale[mt][r0], sh0 = g_shift[mt][r0];
        float sc1 = g_scale[mt][r1], sh1 = g_shift[mt][r1];
#pragma unroll
        for (int j = 0; j < 2; j++) {
            int ncol = n0 + (wn * 2 + j) * 8 + c * 2;
            float v0 = acc1[i][j][0] + acc2[i][j][0] * LO_INV;
            float v1 = acc1[i][j][1] + acc2[i][j][1] * LO_INV;
            float v2 = acc1[i][j][2] + acc2[i][j][2] * LO_INV;
            float v3 = acc1[i][j][3] + acc2[i][j][3] * LO_INV;
            *reinterpret_cast<float2*>(out + (size_t)r0 * NF + ncol) =
                make_float2(v0 * sc0 + sh0, v1 * sc0 + sh0);
            *reinterpret_cast<float2*>(out + (size_t)r1 * NF + ncol) =
                make_float2(v2 * sc1 + sh1, v3 * sc1 + sh1);
        }
    }
}

// ---------------- K3: triple LIF + kv_local (u8 spikes) ----------------
__global__ void k_lif3() {
    int e = blockIdx.x * 256 + threadIdx.x;
    if (e >= PLANE) return;
    int c = e / 800;
    int nb = e - c * 800;
    int bse = c * NF + nb;
    float vq = 0.f, vk = 0.f, vv = 0.f;
    for (int t = 0; t < T_DIM; t++) {
        int off = bse + t * 800;
        float aq = __ldcs(g_yq + off);
        float ak = __ldcs(g_yk + off);
        float av = __ldcs(g_yv + off);
        float q = vq + (aq - vq) * 0.5f;
        float sq = (q >= 1.f) ? 1.f : 0.f;
        vq = q * (1.f - sq);
        float k = vk + (ak - vk) * 0.5f;
        float sk = (k >= 1.f) ? 1.f : 0.f;
        vk = k * (1.f - sk);
        float v = vv + (av - vv) * 0.5f;
        float sv = (v >= 1.f) ? 1.f : 0.f;
        vv = v * (1.f - sv);
        g_qs8[off] = (unsigned char)sq;
        g_kvl8[off] = (unsigned char)(sk * sv);
    }
}

// ---------------- K4: topo routing + LIF(0.5) + SSRE ----------------
__global__ void __launch_bounds__(224) k_topo_ssre() {
    int bid = blockIdx.x;
    int b = bid >> 5;
    int rest = bid & 31;
    int h = rest >> 2;
    int dg = rest & 3;
    int tid = threadIdx.x;

    __shared__ float topo_s[V_DIM * V_DIM];
    __shared__ float kvb[2][200];
    for (int i = tid; i < V_DIM * V_DIM; i += 224) topo_s[i] = g_topo[h][i];

    bool active = tid < 200;
    int d_local = tid / V_DIM;
    int i = tid - d_local * V_DIM;
    int c = h * HD_DIM + dg * 8 + d_local;
    int pbase = c * NF + b * V_DIM + i;

    float dec = 0.f;
    if (active) dec = g_decay[h * HD_DIM + dg * 8 + d_local];
    float omd = 1.f - dec;
    float vm = 0.f, S = 0.f;

    if (active) kvb[0][tid] = (float)g_kvl8[pbase];

    for (int t = 0; t < T_DIM; t++) {
        __syncthreads();
        int cur = t & 1;
        if (t + 1 < T_DIM && active) kvb[cur ^ 1][tid] = (float)g_kvl8[pbase + (t + 1) * 800];
        if (active) {
            const float* kr = &kvb[cur][d_local * V_DIM];
            const float* tr = &topo_s[i * V_DIM];
            float sp = 0.f, sp2 = 0.f;
#pragma unroll
            for (int j = 0; j < 24; j += 2) {
                sp += tr[j] * kr[j];
                sp2 += tr[j + 1] * kr[j + 1];
            }
            sp += tr[24] * kr[24] + sp2;
            vm = vm + (sp - vm) * 0.5f;
            float sk = (vm >= 0.5f) ? 1.f : 0.f;
            vm *= (1.f - sk);
            S = dec * S + omd * sk;
            int off = pbase + t * 800;
            g_qt[off] = g_qs8[off] ? S : 0.f;
        }
    }
}

// ---------------- K6: final LIF(0.5) + identity ----------------
__global__ void k_final(const float* __restrict__ x, float* __restrict__ out) {
    int e = blockIdx.x * 256 + threadIdx.x;
    if (e >= PLANE) return;
    int c = e / 800;
    int nb = e - c * 800;
    int b = nb / V_DIM;
    int v = nb - b * V_DIM;
    int ybase = c * NF + nb;
    int xoff = b * (C_DIM * V_DIM) + c * V_DIM + v;
    float vm = 0.f;
    for (int t = 0; t < T_DIM; t++) {
        float y = __ldcs(g_yq + ybase + t * 800);
        float vv = vm + (y - vm) * 0.5f;
        float s = (vv >= 0.5f) ? 1.f : 0.f;
        vm = vv * (1.f - s);
        int xo = t * PLANE + xoff;
        out[xo] = s + x[xo];
    }
}

// ---------------- launch ----------------
extern "C" void kernel_launch(void* const* d_in, const int* in_sizes, int n_in,
                              void* d_out, int out_size) {
    const float* x = (const float*)d_in[0];
    const float* alpha = (const float*)d_in[1];

    PrepArgs p;
    p.w[0] = (const float*)d_in[2];
    p.w[1] = (const float*)d_in[3];
    p.w[2] = (const float*)d_in[4];

    if (in_sizes[5] == 625) {
        p.base    = (const float*)d_in[5];
        p.learned = (const float*)d_in[6];
        p.sdw     = (const float*)d_in[7];
        p.w[3]    = (const float*)d_in[8];
        p.projb   = (const float*)d_in[9];
        for (int m = 0; m < 4; m++) {
            int o = 10 + m * 4;
            p.gamma[m] = (const float*)d_in[o + 0];
            p.beta[m]  = (const float*)d_in[o + 1];
            p.mean[m]  = (const float*)d_in[o + 2];
            p.var[m]   = (const float*)d_in[o + 3];
        }
    } else {
        for (int m = 0; m < 3; m++) {
            int o = 5 + m * 4;
            p.gamma[m] = (const float*)d_in[o + 0];
            p.beta[m]  = (const float*)d_in[o + 1];
            p.mean[m]  = (const float*)d_in[o + 2];
            p.var[m]   = (const float*)d_in[o + 3];
        }
        p.base    = (const float*)d_in[17];
        p.learned = (const float*)d_in[18];
        p.sdw     = (const float*)d_in[19];
        p.w[3]    = (const float*)d_in[20];
        p.projb   = (const float*)d_in[21];
        p.gamma[3] = (const float*)d_in[22];
        p.beta[3]  = (const float*)d_in[23];
        p.mean[3]  = (const float*)d_in[24];
        p.var[3]   = (const float*)d_in[25];
    }

    float* out = (float*)d_out;

    cudaFuncSetAttribute(k_gemm_mma, cudaFuncAttributeMaxDynamicSharedMemorySize, GSMEM_BYTES);

    GemmArgs ga;
    ga.x = x;

    k_prep<<<6, 256>>>(p);
    k_trans<<<T_DIM * B_DIM, 256>>>(x, alpha);
    k_gemm_mma<<<dim3(NF / BN, C_DIM / BM, 3), GTHREADS, GSMEM_BYTES>>>(ga, 0);
    k_lif3<<<(PLANE + 255) / 256, 256>>>();
    k_topo_ssre<<<B_DIM * H_DIM * 4, 224>>>();
    k_gemm_mma<<<dim3(NF / BN, C_DIM / BM, 1), GTHREADS, GSMEM_BYTES>>>(ga, 1);
    k_final<<<(PLANE + 255) / 256, 256>>>(x, out);
}

// round 14
// speedup vs baseline: 2.5927x; 1.0235x over previous
#include <cuda_runtime.h>
#include <cuda_fp16.h>
#include <math.h>
#include <stdint.h>

typedef unsigned long long ull;

// ---------------- problem constants ----------------
#define T_DIM 64
#define B_DIM 32
#define C_DIM 256
#define V_DIM 25
#define H_DIM 8
#define HD_DIM 32
#define PLANE  (B_DIM * C_DIM * V_DIM)    // 204800
#define TOT    (T_DIM * PLANE)            // 13107200
#define NF     (T_DIM * B_DIM * V_DIM)    // 51200  (GEMM N)
#define BWORDS ((size_t)16 * NF * 8)      // 6,553,600 words per B plane

// ---------------- device scratch ----------------
__device__ __align__(16) float g_yq[TOT];    // q bn-conv out; later proj bn-conv out
__device__ __align__(16) float g_yk[TOT];
__device__ __align__(16) float g_yv[TOT];
__device__ unsigned char g_qs8[TOT];         // q spikes (0/1)
__device__ unsigned char g_kvl8[TOT];        // k_s * v_s (0/1)

// pre-packed weight fragments: [k16 0..15][mf 0..15][lane 0..31][w 0..3]
__device__ __align__(16) uint32_t g_wpkhi[4][32768];
__device__ __align__(16) uint32_t g_wpklo[4][32768];

// pre-packed B fragment planes: word ((K*NF + n)*8 + c2*2 + w) packs
// k = (16K + 8w + 2*c2, +1) at column n, as f16x2. hi/lo split planes.
__device__ __align__(16) uint32_t g_bxhi[BWORDS];
__device__ __align__(16) uint32_t g_bxlo[BWORDS];
__device__ __align__(16) uint32_t g_bqhi[BWORDS];   // qkv_in; later attn
__device__ __align__(16) uint32_t g_bqlo[BWORDS];

__device__ float g_scale[4][C_DIM];
__device__ float g_shift[4][C_DIM];
__device__ float g_topo[H_DIM][V_DIM * V_DIM];
__device__ float g_decay[C_DIM];

// ---------------- helpers ----------------
#define LO_SCALE 1024.0f
#define LO_INV   (1.0f / 1024.0f)

__device__ __forceinline__ void split_h2(float a, float b, uint32_t& h, uint32_t& l) {
    __half ha = __float2half_rn(a), hb = __float2half_rn(b);
    float ra = (a - __half2float(ha)) * LO_SCALE;
    float rb = (b - __half2float(hb)) * LO_SCALE;
    __half la = __float2half_rn(ra), lb = __float2half_rn(rb);
    __half2 hh = __halves2half2(ha, hb), ll = __halves2half2(la, lb);
    h = *reinterpret_cast<uint32_t*>(&hh);
    l = *reinterpret_cast<uint32_t*>(&ll);
}

__device__ __forceinline__ void mma16(float* c, const uint32_t* a, const uint32_t* b) {
    asm volatile(
        "mma.sync.aligned.m16n8k16.row.col.f32.f16.f16.f32 "
        "{%0,%1,%2,%3}, {%4,%5,%6,%7}, {%8,%9}, {%0,%1,%2,%3};"
        : "+f"(c[0]), "+f"(c[1]), "+f"(c[2]), "+f"(c[3])
        : "r"(a[0]), "r"(a[1]), "r"(a[2]), "r"(a[3]), "r"(b[0]), "r"(b[1]));
}

// ---------------- K0: prep ----------------
struct PrepArgs {
    const float* w[4];
    const float* gamma[4];
    const float* beta[4];
    const float* mean[4];
    const float* var[4];
    const float* projb;
    const float* base;
    const float* learned;
    const float* sdw;
};

__global__ void k_prep(PrepArgs p) {
    int blk = blockIdx.x, tid = threadIdx.x;
    if (blk < 4) {
        const float* w = p.w[blk];
        for (int idx = tid; idx < 32768; idx += 256) {
            int k16 = idx >> 11;
            int rest = idx & 2047;
            int mf = rest >> 7;
            int r2 = rest & 127;
            int lane = r2 >> 2;
            int wq = r2 & 3;
            int g = lane >> 2, c = lane & 3;
            int row = mf * 16 + g + (wq & 1) * 8;
            int col = k16 * 16 + 2 * c + ((wq & 2) ? 8 : 0);
            uint32_t hi, lo;
            split_h2(w[row * C_DIM + col], w[row * C_DIM + col + 1], hi, lo);
            g_wpkhi[blk][idx] = hi;
            g_wpklo[blk][idx] = lo;
        }
        float sc = p.gamma[blk][tid] * rsqrtf(p.var[blk][tid] + 1e-5f);
        float sh = p.beta[blk][tid] - p.mean[blk][tid] * sc;
        if (blk == 3) sh += p.projb[tid] * sc;
        g_scale[blk][tid] = sc;
        g_shift[blk][tid] = sh;
    } else if (blk == 4) {
        if (tid < H_DIM * V_DIM) {
            int h = tid / V_DIM, i = tid - h * V_DIM;
            float l[V_DIM];
            float mx = -1e30f;
            for (int j = 0; j < V_DIM; j++) {
                l[j] = p.base[i * V_DIM + j] + 0.5f * p.learned[(h * V_DIM + i) * V_DIM + j];
                mx = fmaxf(mx, l[j]);
            }
            float sum = 0.f;
            for (int j = 0; j < V_DIM; j++) { l[j] = expf(l[j] - mx); sum += l[j]; }
            float inv = 1.f / sum;
            for (int j = 0; j < V_DIM; j++) g_topo[h][i * V_DIM + j] = l[j] * inv;
        }
    } else {
        float w = p.sdw[tid];
        float sg = 1.f / (1.f + expf(-w));
        g_decay[tid] = fminf(0.99f, fmaxf(0.01f, sg));
    }
}

// ---------------- K1: transpose + split-pack x and qkv_in ----------------
// One block per (t,b). dyn smem: sxf[6400] + sqf[6400].
__global__ void k_trans(const float* __restrict__ x, const float* __restrict__ alpha) {
    extern __shared__ float dynsm[];
    float* sxf = dynsm;
    float* sqf = dynsm + C_DIM * V_DIM;
    __shared__ float alp[C_DIM];
    int tid = threadIdx.x;
    alp[tid] = alpha[tid];
    __syncthreads();

    int t = blockIdx.x >> 5;
    int b = blockIdx.x & 31;
    const float* xin = x + (size_t)t * PLANE + b * (C_DIM * V_DIM);
    const float* xpr = xin - PLANE;
    int nbase = t * 800 + b * V_DIM;

    for (int idx = tid; idx < C_DIM * V_DIM; idx += 256) {
        int c = idx / V_DIM;
        float xv = xin[idx];
        float g = (t == 0) ? 0.f : fabsf(xv - xpr[idx]);
        float a = alp[c];
        sxf[idx] = xv;
        sqf[idx] = a * g + (1.f - a) * xv;
    }
    __syncthreads();

    for (int widx = tid; widx < V_DIM * 128; widx += 256) {
        int v = widx >> 7, j = widx & 127;
        int base = 2 * j * V_DIM + v;
        int K = j >> 3;
        int c2w = ((j & 3) << 1) | ((j >> 2) & 1);
        size_t addr = ((size_t)K * NF + (nbase + v)) * 8 + c2w;
        uint32_t h, l;
        split_h2(sxf[base], sxf[base + V_DIM], h, l);
        g_bxhi[addr] = h; g_bxlo[addr] = l;
        split_h2(sqf[base], sqf[base + V_DIM], h, l);
        g_bqhi[addr] = h; g_bqlo[addr] = l;
    }
}

// ---------------- K2/K5: fp16x3 mma.sync GEMM + fused BN ----------------
// Block tile 128x64, BK=32, 256 threads (8 warps), warp tile 64x16, 2 CTA/SM.
// Both A and B staged from pre-packed fragment planes (pure copy).
#define BM 128
#define BN 64
#define BK 32
#define GTHREADS 256
#define AH_OFF 0
#define AL_OFF 2048
#define BH_OFF 4096
#define BL_OFF 5120
#define BUF_WORDS 6144
#define GSMEM_BYTES (2 * BUF_WORDS * 4)

__device__ __forceinline__ void stage_load(const uint32_t* __restrict__ Ahi, const uint32_t* __restrict__ Alo,
                                           const uint32_t* __restrict__ Bhi, const uint32_t* __restrict__ Blo,
                                           size_t bfrag, int kc, int yoff, int tid,
                                           uint4* ah4, uint4* al4, uint2* bh2, uint2* bl2) {
#pragma unroll
    for (int kf = 0; kf < 2; kf++) {
        size_t abase = ((size_t)((kc * 2 + kf) * 16 + yoff + (tid >> 5)) << 7) + (tid & 31) * 4;
        ah4[kf] = *reinterpret_cast<const uint4*>(Ahi + abase);
        al4[kf] = *reinterpret_cast<const uint4*>(Alo + abase);
        size_t baddr = (size_t)(kc * 2 + kf) * (NF * 8) + bfrag;
        bh2[kf] = *reinterpret_cast<const uint2*>(Bhi + baddr);
        bl2[kf] = *reinterpret_cast<const uint2*>(Blo + baddr);
    }
}

__device__ __forceinline__ void stage_store(uint32_t* sb, int tid,
                                            const uint4* ah4, const uint4* al4,
                                            const uint2* bh2, const uint2* bl2) {
#pragma unroll
    for (int kf = 0; kf < 2; kf++) {
        *reinterpret_cast<uint4*>(sb + AH_OFF + kf * 1024 + tid * 4) = ah4[kf];
        *reinterpret_cast<uint4*>(sb + AL_OFF + kf * 1024 + tid * 4) = al4[kf];
        *reinterpret_cast<uint2*>(sb + BH_OFF + kf * 512 + tid * 2) = bh2[kf];
        *reinterpret_cast<uint2*>(sb + BL_OFF + kf * 512 + tid * 2) = bl2[kf];
    }
}

__global__ void __launch_bounds__(GTHREADS, 2) k_gemm_mma(int pass) {
    extern __shared__ uint32_t sm32[];
    int mt;
    const uint32_t* Bhi;
    const uint32_t* Blo;
    float* out;
    if (pass == 0) {
        mt = blockIdx.z;
        if (mt == 2) { Bhi = g_bxhi; Blo = g_bxlo; }
        else         { Bhi = g_bqhi; Blo = g_bqlo; }
        out = (mt == 0) ? g_yq : (mt == 1) ? g_yk : g_yv;
    } else {
        mt = 3;
        Bhi = g_bqhi; Blo = g_bqlo;
        out = g_yq;
    }
    const uint32_t* Ahi = g_wpkhi[mt];
    const uint32_t* Alo = g_wpklo[mt];
    int m0 = blockIdx.y * BM;
    int yoff = blockIdx.y * 8;
    int n0 = blockIdx.x * BN;
    int tid = threadIdx.x;
    int lane = tid & 31, wid = tid >> 5;
    int wm = wid >> 2;
    int wn = wid & 3;

    // per-thread B fragment offset within one K-plane: ((n)*8 + c*2)
    size_t bfrag;
    {
        int nf = tid >> 5, g2 = (tid & 31) >> 2, cc = tid & 3;
        bfrag = (size_t)(n0 + nf * 8 + g2) * 8 + cc * 2;
    }

    float acc1[4][2][4], acc2[4][2][4];
#pragma unroll
    for (int i = 0; i < 4; i++)
#pragma unroll
        for (int j = 0; j < 2; j++)
#pragma unroll
            for (int r = 0; r < 4; r++) { acc1[i][j][r] = 0.f; acc2[i][j][r] = 0.f; }

    uint4 ah4[2], al4[2];
    uint2 bh2[2], bl2[2];
    stage_load(Ahi, Alo, Bhi, Blo, bfrag, 0, yoff, tid, ah4, al4, bh2, bl2);
    stage_store(sm32, tid, ah4, al4, bh2, bl2);
    __syncthreads();

    for (int kc = 0; kc < C_DIM / BK; kc++) {
        uint32_t* sb = sm32 + (kc & 1) * BUF_WORDS;
        bool more = (kc + 1 < C_DIM / BK);
        if (more) stage_load(Ahi, Alo, Bhi, Blo, bfrag, kc + 1, yoff, tid, ah4, al4, bh2, bl2);

#pragma unroll
        for (int kf = 0; kf < 2; kf++) {
            uint32_t Bh[2][2], Bl[2][2];
#pragma unroll
            for (int j = 0; j < 2; j++) {
                int fi = kf * 512 + ((wn * 2 + j) * 32 + lane) * 2;
                uint2 bh = *reinterpret_cast<const uint2*>(sb + BH_OFF + fi);
                uint2 bl = *reinterpret_cast<const uint2*>(sb + BL_OFF + fi);
                Bh[j][0] = bh.x; Bh[j][1] = bh.y;
                Bl[j][0] = bl.x; Bl[j][1] = bl.y;
            }
#pragma unroll
            for (int i = 0; i < 4; i++) {
                int fi = kf * 1024 + ((wm * 4 + i) * 32 + lane) * 4;
                uint4 a4 = *reinterpret_cast<const uint4*>(sb + AH_OFF + fi);
                uint4 l4 = *reinterpret_cast<const uint4*>(sb + AL_OFF + fi);
                uint32_t Ah[4] = {a4.x, a4.y, a4.z, a4.w};
                uint32_t Al[4] = {l4.x, l4.y, l4.z, l4.w};
#pragma unroll
                for (int j = 0; j < 2; j++) {
                    mma16(acc1[i][j], Ah, Bh[j]);
                    mma16(acc2[i][j], Ah, Bl[j]);
                    mma16(acc2[i][j], Al, Bh[j]);
                }
            }
        }
        if (more) stage_store(sm32 + ((kc + 1) & 1) * BUF_WORDS, tid, ah4, al4, bh2, bl2);
        __syncthreads();
    }

    int g = lane >> 2, c = lane & 3;
#pragma unroll
    for (int i = 0; i < 4; i++) {
        int r0 = m0 + wm * 64 + i * 16 + g;
        int r1 = r0 + 8;
        float sc0 = g_scale[mt][r0], sh0 = g_shift[mt][r0];
        float sc1 = g_scale[mt][r1], sh1 = g_shift[mt][r1];
#pragma unroll
        for (int j = 0; j < 2; j++) {
            int ncol = n0 + (wn * 2 + j) * 8 + c * 2;
            float v0 = acc1[i][j][0] + acc2[i][j][0] * LO_INV;
            float v1 = acc1[i][j][1] + acc2[i][j][1] * LO_INV;
            float v2 = acc1[i][j][2] + acc2[i][j][2] * LO_INV;
            float v3 = acc1[i][j][3] + acc2[i][j][3] * LO_INV;
            *reinterpret_cast<float2*>(out + (size_t)r0 * NF + ncol) =
                make_float2(v0 * sc0 + sh0, v1 * sc0 + sh0);
            *reinterpret_cast<float2*>(out + (size_t)r1 * NF + ncol) =
                make_float2(v2 * sc1 + sh1, v3 * sc1 + sh1);
        }
    }
}

// ---------------- K3: triple LIF + kv_local (u8 spikes) ----------------
__global__ void k_lif3() {
    int e = blockIdx.x * 256 + threadIdx.x;
    if (e >= PLANE) return;
    int c = e / 800;
    int nb = e - c * 800;
    int bse = c * NF + nb;
    float vq = 0.f, vk = 0.f, vv = 0.f;
    for (int t = 0; t < T_DIM; t++) {
        int off = bse + t * 800;
        float aq = __ldcs(g_yq + off);
        float ak = __ldcs(g_yk + off);
        float av = __ldcs(g_yv + off);
        float q = vq + (aq - vq) * 0.5f;
        float sq = (q >= 1.f) ? 1.f : 0.f;
        vq = q * (1.f - sq);
        float k = vk + (ak - vk) * 0.5f;
        float sk = (k >= 1.f) ? 1.f : 0.f;
        vk = k * (1.f - sk);
        float v = vv + (av - vv) * 0.5f;
        float sv = (v >= 1.f) ? 1.f : 0.f;
        vv = v * (1.f - sv);
        g_qs8[off] = (unsigned char)sq;
        g_kvl8[off] = (unsigned char)(sk * sv);
    }
}

// ---------------- K4: topo routing + LIF(0.5) + SSRE -> packed attn ----------------
__global__ void __launch_bounds__(224) k_topo_ssre() {
    int bid = blockIdx.x;
    int b = bid >> 5;
    int rest = bid & 31;
    int h = rest >> 2;
    int dg = rest & 3;
    int tid = threadIdx.x;

    __shared__ float topo_s[V_DIM * V_DIM];
    __shared__ float kvb[2][200];
    __shared__ float satt[200];
    for (int i = tid; i < V_DIM * V_DIM; i += 224) topo_s[i] = g_topo[h][i];

    bool active = tid < 200;
    int d_local = tid / V_DIM;
    int i = tid - d_local * V_DIM;
    int c = h * HD_DIM + dg * 8 + d_local;
    int pbase = c * NF + b * V_DIM + i;
    int cb = h * HD_DIM + dg * 8;

    // packer indices (threads 0..99)
    bool packer = tid < 100;
    int pp = tid >> 0;  // computed below
    int pi = 0, pj = 0;
    size_t paddr_base = 0;
    if (packer) {
        int p = tid / V_DIM;          // 0..3
        pi = tid - p * V_DIM;         // 0..24
        pj = (cb >> 1) + p;           // global k-pair index
        int K = pj >> 3;
        int c2w = ((pj & 3) << 1) | ((pj >> 2) & 1);
        paddr_base = ((size_t)K * NF + b * V_DIM + pi) * 8 + c2w;
        pp = p;
    }

    float dec = 0.f;
    if (active) dec = g_decay[h * HD_DIM + dg * 8 + d_local];
    float omd = 1.f - dec;
    float vm = 0.f, S = 0.f;

    if (active) kvb[0][tid] = (float)g_kvl8[pbase];

    for (int t = 0; t < T_DIM; t++) {
        __syncthreads();
        int cur = t & 1;
        if (t + 1 < T_DIM && active) kvb[cur ^ 1][tid] = (float)g_kvl8[pbase + (t + 1) * 800];
        if (active) {
            const float* kr = &kvb[cur][d_local * V_DIM];
            const float* tr = &topo_s[i * V_DIM];
            float sp = 0.f, sp2 = 0.f;
#pragma unroll
            for (int j = 0; j < 24; j += 2) {
                sp += tr[j] * kr[j];
                sp2 += tr[j + 1] * kr[j + 1];
            }
            sp += tr[24] * kr[24] + sp2;
            vm = vm + (sp - vm) * 0.5f;
            float sk = (vm >= 0.5f) ? 1.f : 0.f;
            vm *= (1.f - sk);
            S = dec * S + omd * sk;
            satt[tid] = g_qs8[pbase + t * 800] ? S : 0.f;
        }
        __syncthreads();
        if (packer) {
            float f0 = satt[(2 * pp) * V_DIM + pi];
            float f1 = satt[(2 * pp + 1) * V_DIM + pi];
            uint32_t hw, lw;
            split_h2(f0, f1, hw, lw);
            size_t addr = paddr_base + (size_t)t * (800 * 8);
            g_bqhi[addr] = hw;
            g_bqlo[addr] = lw;
        }
    }
}

// ---------------- K6: final LIF(0.5) + identity ----------------
__global__ void k_final(const float* __restrict__ x, float* __restrict__ out) {
    int e = blockIdx.x * 256 + threadIdx.x;
    if (e >= PLANE) return;
    int c = e / 800;
    int nb = e - c * 800;
    int b = nb / V_DIM;
    int v = nb - b * V_DIM;
    int ybase = c * NF + nb;
    int xoff = b * (C_DIM * V_DIM) + c * V_DIM + v;
    float vm = 0.f;
    for (int t = 0; t < T_DIM; t++) {
        float y = __ldcs(g_yq + ybase + t * 800);
        float vv = vm + (y - vm) * 0.5f;
        float s = (vv >= 0.5f) ? 1.f : 0.f;
        vm = vv * (1.f - s);
        int xo = t * PLANE + xoff;
        out[xo] = s + x[xo];
    }
}

// ---------------- launch ----------------
extern "C" void kernel_launch(void* const* d_in, const int* in_sizes, int n_in,
                              void* d_out, int out_size) {
    const float* x = (const float*)d_in[0];
    const float* alpha = (const float*)d_in[1];

    PrepArgs p;
    p.w[0] = (const float*)d_in[2];
    p.w[1] = (const float*)d_in[3];
    p.w[2] = (const float*)d_in[4];

    if (in_sizes[5] == 625) {
        p.base    = (const float*)d_in[5];
        p.learned = (const float*)d_in[6];
        p.sdw     = (const float*)d_in[7];
        p.w[3]    = (const float*)d_in[8];
        p.projb   = (const float*)d_in[9];
        for (int m = 0; m < 4; m++) {
            int o = 10 + m * 4;
            p.gamma[m] = (const float*)d_in[o + 0];
            p.beta[m]  = (const float*)d_in[o + 1];
            p.mean[m]  = (const float*)d_in[o + 2];
            p.var[m]   = (const float*)d_in[o + 3];
        }
    } else {
        for (int m = 0; m < 3; m++) {
            int o = 5 + m * 4;
            p.gamma[m] = (const float*)d_in[o + 0];
            p.beta[m]  = (const float*)d_in[o + 1];
            p.mean[m]  = (const float*)d_in[o + 2];
            p.var[m]   = (const float*)d_in[o + 3];
        }
        p.base    = (const float*)d_in[17];
        p.learned = (const float*)d_in[18];
        p.sdw     = (const float*)d_in[19];
        p.w[3]    = (const float*)d_in[20];
        p.projb   = (const float*)d_in[21];
        p.gamma[3] = (const float*)d_in[22];
        p.beta[3]  = (const float*)d_in[23];
        p.mean[3]  = (const float*)d_in[24];
        p.var[3]   = (const float*)d_in[25];
    }

    float* out = (float*)d_out;

    cudaFuncSetAttribute(k_gemm_mma, cudaFuncAttributeMaxDynamicSharedMemorySize, GSMEM_BYTES);
    int tsm = 2 * C_DIM * V_DIM * 4;   // 51200 B
    cudaFuncSetAttribute(k_trans, cudaFuncAttributeMaxDynamicSharedMemorySize, tsm);

    k_prep<<<6, 256>>>(p);
    k_trans<<<T_DIM * B_DIM, 256, tsm>>>(x, alpha);
    k_gemm_mma<<<dim3(NF / BN, C_DIM / BM, 3), GTHREADS, GSMEM_BYTES>>>(0);
    k_lif3<<<(PLANE + 255) / 256, 256>>>();
    k_topo_ssre<<<B_DIM * H_DIM * 4, 224>>>();
    k_gemm_mma<<<dim3(NF / BN, C_DIM / BM, 1), GTHREADS, GSMEM_BYTES>>>(1);
    k_final<<<(PLANE + 255) / 256, 256>>>(x, out);
}